// round 14
// baseline (speedup 1.0000x reference)
#include <cuda_runtime.h>
#include <cuda_bf16.h>
#include <cstdint>

#define P_  128
#define D_  128
#define R_  16384
#define E_  131072
#define T_  1024
#define F_  513
#define FP_ 520     // padded row stride in float2 (16B-aligned rows)
#define CH_ 128     // f-chunk (complex freqs); 4 chunks cover f 0..511

// ---------------- scratch (static device allocations; no cudaMalloc) ----------
static __device__ __align__(16) float2 g_bufA[R_*FP_ + 256];   // r_k
static __device__ __align__(16) float2 g_bufB[R_*FP_ + 256];   // prop * (K r)
static __device__ __align__(16) float  g_K[P_*D_*D_];          // [p][e][d] (f=512 path)
static __device__ __align__(16) uint4  g_AfragHi[P_*8*8*32];   // mma-fragment-ordered K (hi)
static __device__ __align__(16) uint4  g_AfragLo[P_*8*8*32];   // mma-fragment-ordered K (lo)
static __device__ __align__(16) int g_rowptr[R_+4];
static __device__ __align__(16) int g_rowcnt[R_];              // zeroed by k_ifft each call
static __device__ int    g_cols[E_];
static __device__ float  g_vals[E_];
static __device__ float  g_echo[2*F_];
static __device__ float  g_time[T_];

// ---------------- constants matching reference fp32 rounding ------------------
__device__ __forceinline__ float c_s32()  { return (float)(16000.0/343.0); }
__device__ __forceinline__ float c_c32()  { return (float)(-2.0*3.14159265358979323846/1024.0); }
__device__ __forceinline__ float c_kdec() { return (float)(-6.907755278982137/343.0 - 0.001); }
#define LOG_GAMMA_F (-6.907755278982137f)

__device__ __forceinline__ void sc_big(float x, float& s, float& c) {
    float k = rintf(x * 0.15915494309189535f);
    float r = fmaf(k, -6.28125f, x);
    r = fmaf(k, -1.9353071795864769e-3f, r);
    __sincosf(r, &s, &c);
}

__device__ __forceinline__ float2 cmul(float2 a, float2 b) {
    return make_float2(a.x*b.x - a.y*b.y, a.x*b.y + a.y*b.x);
}

__device__ __forceinline__ uint32_t smem_u32(const void* p) {
    uint32_t a;
    asm("{ .reg .u64 t; cvta.to.shared.u64 t, %1; cvt.u32.u64 %0, t; }" : "=r"(a) : "l"(p));
    return a;
}

__device__ __forceinline__ uint32_t pk_bf2(float a, float b) {
    __nv_bfloat16 ha = __float2bfloat16(a), hb = __float2bfloat16(b);
    return ((uint32_t)__bfloat16_as_ushort(hb) << 16) | __bfloat16_as_ushort(ha);
}
__device__ __forceinline__ uint32_t pk_bf2_lo(float a, float b) {
    __nv_bfloat16 ha = __float2bfloat16(a), hb = __float2bfloat16(b);
    float ra = a - __bfloat162float(ha);
    float rb = b - __bfloat162float(hb);
    __nv_bfloat16 la = __float2bfloat16(ra), lb = __float2bfloat16(rb);
    return ((uint32_t)__bfloat16_as_ushort(lb) << 16) | __bfloat16_as_ushort(la);
}

// base-ISA tensor ops (sm_80+/75+, valid in compute_103 PTX)
__device__ __forceinline__ void mma_bf16(float& d0, float& d1, float& d2, float& d3,
                                         uint32_t a0, uint32_t a1, uint32_t a2, uint32_t a3,
                                         uint32_t b0, uint32_t b1) {
    asm volatile("mma.sync.aligned.m16n8k16.row.col.f32.bf16.bf16.f32 "
                 "{%0,%1,%2,%3}, {%4,%5,%6,%7}, {%8,%9}, {%0,%1,%2,%3};"
                 : "+f"(d0), "+f"(d1), "+f"(d2), "+f"(d3)
                 : "r"(a0), "r"(a1), "r"(a2), "r"(a3), "r"(b0), "r"(b1));
}
__device__ __forceinline__ void ldsm_x4_t(uint32_t& r0, uint32_t& r1, uint32_t& r2, uint32_t& r3,
                                          uint32_t addr) {
    asm volatile("ldmatrix.sync.aligned.m8n8.x4.trans.shared.b16 {%0,%1,%2,%3}, [%4];"
                 : "=r"(r0), "=r"(r1), "=r"(r2), "=r"(r3) : "r"(addr));
}

// ---------------- fused setup: K (fp32 + mma frags), zeros, CSR hist ----------
__global__ void k_setup(const float* __restrict__ basis, const float* __restrict__ absorb,
                        const float* __restrict__ scat, const int* __restrict__ obj,
                        const int* __restrict__ gkr) {
    int idx = blockIdx.x * blockDim.x + threadIdx.x;
    if (idx < 2*F_) g_echo[idx] = 0.0f;
    if (idx < T_)   g_time[idx] = 0.0f;
    if (idx < E_)   atomicAdd(&g_rowcnt[gkr[idx]], 1);   // rowcnt pre-zeroed (static / k_ifft)

    if (idx < P_*8*8*32) {   // mma-fragment-ordered bf16 hi/lo A
        int lane = idx & 31;
        int dt = (idx >> 5) & 7;
        int s  = (idx >> 8) & 7;
        int p  = idx >> 11;
        int o = obj[p];
        float refl = 1.0f - absorb[o];
        float c0 = refl * scat[o];
        float c1 = refl * (1.0f - scat[o]);
        int r  = lane >> 2, cq = lane & 3;
        int d0 = dt*16 + r, d1 = d0 + 8;
        int k0 = s*16 + cq*2;
#define KV(d, e) (c0 * basis[(d)*D_ + (e)] + c1 * basis[D_*D_ + (d)*D_ + (e)])
        float v00 = KV(d0, k0),     v01 = KV(d0, k0+1);
        float v10 = KV(d1, k0),     v11 = KV(d1, k0+1);
        float v02 = KV(d0, k0+8),   v03 = KV(d0, k0+9);
        float v12 = KV(d1, k0+8),   v13 = KV(d1, k0+9);
        g_AfragHi[idx] = make_uint4(pk_bf2(v00,v01), pk_bf2(v10,v11),
                                    pk_bf2(v02,v03), pk_bf2(v12,v13));
        g_AfragLo[idx] = make_uint4(pk_bf2_lo(v00,v01), pk_bf2_lo(v10,v11),
                                    pk_bf2_lo(v02,v03), pk_bf2_lo(v12,v13));
    }

    if (idx >= P_*D_*D_) return;
    {   // fp32 K for the f=512 path
        int p = idx / (D_*D_);
        int rem = idx - p*D_*D_;
        int e = rem / D_;
        int d = rem - e*D_;
        int o = obj[p];
        float refl = 1.0f - absorb[o];
        float c0 = refl * scat[o];
        float c1 = refl * (1.0f - scat[o]);
        g_K[idx] = c0 * basis[d*D_ + e] + c1 * basis[D_*D_ + d*D_ + e];
#undef KV
    }
}

__global__ void __launch_bounds__(1024) k_scan() {
    __shared__ int wsum[32];
    int t = threadIdx.x, lane = t & 31, wid = t >> 5;
    int4 v[4];
    const int4* src = (const int4*)g_rowcnt;
#pragma unroll
    for (int i = 0; i < 4; i++) v[i] = src[t*4 + i];
    const int* x = (const int*)v;
    int loc[16], sum = 0;
#pragma unroll
    for (int i = 0; i < 16; i++) { loc[i] = sum; sum += x[i]; }
    int incl = sum;
#pragma unroll
    for (int off = 1; off < 32; off <<= 1) {
        int n = __shfl_up_sync(0xffffffffu, incl, off);
        if (lane >= off) incl += n;
    }
    if (lane == 31) wsum[wid] = incl;
    __syncthreads();
    if (wid == 0) {
        int ws = wsum[lane];
#pragma unroll
        for (int off = 1; off < 32; off <<= 1) {
            int n = __shfl_up_sync(0xffffffffu, ws, off);
            if (lane >= off) ws += n;
        }
        wsum[lane] = ws;
    }
    __syncthreads();
    int off0 = (wid > 0 ? wsum[wid-1] : 0) + (incl - sum);
    int4 o[4];
    int* op = (int*)o;
#pragma unroll
    for (int i = 0; i < 16; i++) op[i] = off0 + loc[i];
    int4* dst = (int4*)g_rowptr;
    int4* cz  = (int4*)g_rowcnt;
    int4 z = make_int4(0,0,0,0);
#pragma unroll
    for (int i = 0; i < 4; i++) { dst[t*4 + i] = o[i]; cz[t*4 + i] = z; }
    if (t == 1023) g_rowptr[R_] = wsum[31];
}

__global__ void k_scatter(const int* __restrict__ gkr, const int* __restrict__ gkc,
                          const float* __restrict__ gkv) {
    int e = blockIdx.x * blockDim.x + threadIdx.x;
    if (e >= E_) return;
    int r = gkr[e];
    int pos = g_rowptr[r] + atomicAdd(&g_rowcnt[r], 1);
    g_cols[pos] = gkc[e];
    g_vals[pos] = gkv[e];
}

// ---------------- rad: bufA = rad (full F), echo += w_rec*pf_rec*rad ----------
__global__ void __launch_bounds__(256) k_rad(const float* __restrict__ rpos,
                                             const float* __restrict__ spos,
                                             const float* __restrict__ rcpos) {
    __shared__ __align__(16) float2 esh[8][520];
    int w = threadIdx.x >> 5, lane = threadIdx.x & 31;
    int row = blockIdx.x * 8 + w;

    float px = rpos[3*row+0], py = rpos[3*row+1], pz = rpos[3*row+2];
    float dx = px - spos[0], dy = py - spos[1], dz = pz - spos[2];
    float ds = sqrtf(dx*dx + dy*dy + dz*dz);
    float bs = c_c32() * (ds * c_s32());
    float amp = __expf(c_kdec() * ds) / (ds*ds + 0.001f);

    float rx = px - rcpos[0], ry = py - rcpos[1], rz = pz - rcpos[2];
    float dr = sqrtf(rx*rx + ry*ry + rz*rz);
    float br = c_c32() * (dr * c_s32());
    float wamp = __expf(c_kdec() * dr) / (dr*dr + 0.001f);

    float s0, c0;
    sc_big(bs * (float)lane, s0, c0);
    float2 wsrc = make_float2(c0, s0);
    sc_big(bs * 32.0f, s0, c0);
    float2 wsstep = make_float2(c0, s0);
    sc_big(br * (float)lane, s0, c0);
    float2 wrec = make_float2(c0, s0);
    sc_big(br * 32.0f, s0, c0);
    float2 wrstep = make_float2(c0, s0);

#pragma unroll
    for (int k = 0; k < 16; k++) {
        int f = k*32 + lane;
        float2 rad = make_float2(amp * wsrc.x, amp * wsrc.y);
        g_bufA[(size_t)row*FP_ + f] = rad;
        float2 er = cmul(rad, wrec);
        esh[w][f] = make_float2(wamp * er.x, wamp * er.y);
        wsrc = cmul(wsrc, wsstep);
        wrec = cmul(wrec, wrstep);
    }
    if (lane == 0) {
        float2 rad = make_float2(amp * wsrc.x, amp * wsrc.y);
        g_bufA[(size_t)row*FP_ + 512] = rad;
        float2 er = cmul(rad, wrec);
        esh[w][512] = make_float2(wamp * er.x, wamp * er.y);
    }
    __syncthreads();
    for (int f = threadIdx.x; f < F_; f += 256) {
        float sr = 0.0f, si = 0.0f;
#pragma unroll
        for (int ww = 0; ww < 8; ww++) { sr += esh[ww][f].x; si += esh[ww][f].y; }
        atomicAdd(&g_echo[2*f  ], sr);
        atomicAdd(&g_echo[2*f+1], si);
    }
}

// ---------------- tensor GEMM chunk: bufB[ch] = prop * (K_p @ bufA[ch]) -------
// grid (P_, 4) per chunk; block D[128d x 64n]; warps 8d x 2n; 512 thr, 2/SM.
#define BP_ 144
__global__ void __launch_bounds__(512, 2) k_gemm_tc(const float* __restrict__ avg_dist,
                                                    int fbase) {
    __shared__ __align__(16) unsigned char Bhi[128*BP_];
    __shared__ __align__(16) unsigned char Blo[128*BP_];
    int p = blockIdx.x, f0 = fbase + blockIdx.y*32;
    int tid = threadIdx.x, w = tid >> 5, lane = tid & 31;
    int wd = w & 7, wn = w >> 3;

    {
        int k = tid >> 2, q = tid & 3;
        const float4* src = (const float4*)(g_bufA + (size_t)(p*128 + k)*FP_ + f0) + q*4;
        uint32_t hi[8], lo[8];
#pragma unroll
        for (int j = 0; j < 4; j++) {
            float4 v = src[j];
            hi[2*j]   = pk_bf2(v.x, v.y);
            hi[2*j+1] = pk_bf2(v.z, v.w);
            lo[2*j]   = pk_bf2_lo(v.x, v.y);
            lo[2*j+1] = pk_bf2_lo(v.z, v.w);
        }
        uint4* dh = (uint4*)(Bhi + k*BP_ + q*32);
        uint4* dl = (uint4*)(Blo + k*BP_ + q*32);
        dh[0] = make_uint4(hi[0], hi[1], hi[2], hi[3]);
        dh[1] = make_uint4(hi[4], hi[5], hi[6], hi[7]);
        dl[0] = make_uint4(lo[0], lo[1], lo[2], lo[3]);
        dl[1] = make_uint4(lo[4], lo[5], lo[6], lo[7]);
    }
    __syncthreads();

    float acc[4][4];
#pragma unroll
    for (int j = 0; j < 4; j++)
#pragma unroll
        for (int q = 0; q < 4; q++) acc[j][q] = 0.0f;

    int g = lane >> 3, lr = lane & 7;
    uint32_t rowoff = (uint32_t)(((g & 1)*8 + lr) * BP_);
    uint32_t bs_hi = smem_u32(Bhi), bs_lo = smem_u32(Blo);
    uint32_t co0 = bs_hi + rowoff + (uint32_t)((wn*32 +  0 + (g >> 1)*8) * 2);
    uint32_t co1 = bs_hi + rowoff + (uint32_t)((wn*32 + 16 + (g >> 1)*8) * 2);
    uint32_t cl0 = bs_lo + rowoff + (uint32_t)((wn*32 +  0 + (g >> 1)*8) * 2);
    uint32_t cl1 = bs_lo + rowoff + (uint32_t)((wn*32 + 16 + (g >> 1)*8) * 2);

    const uint4* Ah = g_AfragHi + ((size_t)p * 8) * 8 * 32;
    const uint4* Al = g_AfragLo + ((size_t)p * 8) * 8 * 32;

#pragma unroll
    for (int s = 0; s < 8; s++) {
        uint4 ah = Ah[((s*8) + wd)*32 + lane];
        uint4 al = Al[((s*8) + wd)*32 + lane];
        uint32_t soff = (uint32_t)(s * 16 * BP_);
        uint32_t bh[8], bl[8];
        ldsm_x4_t(bh[0], bh[1], bh[2], bh[3], co0 + soff);
        ldsm_x4_t(bh[4], bh[5], bh[6], bh[7], co1 + soff);
        ldsm_x4_t(bl[0], bl[1], bl[2], bl[3], cl0 + soff);
        ldsm_x4_t(bl[4], bl[5], bl[6], bl[7], cl1 + soff);
#pragma unroll
        for (int nt = 0; nt < 4; nt++) {
            mma_bf16(acc[nt][0], acc[nt][1], acc[nt][2], acc[nt][3],
                     ah.x, ah.y, ah.z, ah.w, bh[2*nt], bh[2*nt+1]);
            mma_bf16(acc[nt][0], acc[nt][1], acc[nt][2], acc[nt][3],
                     ah.x, ah.y, ah.z, ah.w, bl[2*nt], bl[2*nt+1]);
            mma_bf16(acc[nt][0], acc[nt][1], acc[nt][2], acc[nt][3],
                     al.x, al.y, al.z, al.w, bh[2*nt], bh[2*nt+1]);
        }
    }

    int r0 = lane >> 2, fq = lane & 3;
#pragma unroll
    for (int half = 0; half < 2; half++) {
        int d = wd*16 + half*8 + r0;
        int row = p*128 + d;
        float dist = avg_dist[row];
        float b = c_c32() * (dist * c_s32());
        float dec = __expf(c_kdec() * dist);
        float2* outp = g_bufB + (size_t)row*FP_ + f0 + wn*16;
        int fb = f0 + wn*16 + fq;
        float ss, cc;
        sc_big(b * (float)fb, ss, cc);
        float2 wp = make_float2(dec * cc, dec * ss);
        sc_big(b * 4.0f, ss, cc);
        float2 wst = make_float2(cc, ss);
#pragma unroll
        for (int nt = 0; nt < 4; nt++) {
            float2 v = cmul(make_float2(acc[nt][half*2 + 0], acc[nt][half*2 + 1]), wp);
            outp[nt*4 + fq] = v;
            wp = cmul(wp, wst);
        }
    }
}

// f = 512 column only (fp32 path)
__global__ void __launch_bounds__(128) k_gemm_last(const float* __restrict__ avg_dist) {
    __shared__ float2 xs[128];
    int p = blockIdx.x, d = threadIdx.x;
    xs[d] = g_bufA[(size_t)(p*128 + d)*FP_ + 512];
    __syncthreads();
    const float* Kp = g_K + (size_t)p * D_ * D_;
    float ar = 0.0f, ai = 0.0f;
#pragma unroll 8
    for (int e = 0; e < 128; e++) {
        float kv = Kp[e*128 + d];
        float2 x = xs[e];
        ar = fmaf(kv, x.x, ar);
        ai = fmaf(kv, x.y, ai);
    }
    int row = p*128 + d;
    float dist = avg_dist[row];
    float b = c_c32() * (dist * c_s32());
    float dec = __expf(c_kdec() * dist);
    float ss, cc; sc_big(b * 512.0f, ss, cc);
    float pr = dec * cc, pi = dec * ss;
    g_bufB[(size_t)row*FP_ + 512] = make_float2(pr*ar - pi*ai, pr*ai + pi*ar);
}

// ---------------- SpMM chunk: bufA[ch] = A @ bufB[ch], echo += ... ------------
__global__ void __launch_bounds__(256) k_spmm(const float* __restrict__ rpos,
                                              const float* __restrict__ rcpos,
                                              int fbase) {
    __shared__ __align__(16) float2 esh[8][CH_ + 8];
    int w = threadIdx.x >> 5, lane = threadIdx.x & 31;
    int row = blockIdx.x * 8 + w;
    int s = g_rowptr[row], e = g_rowptr[row+1];

    float4 acc0 = make_float4(0.f,0.f,0.f,0.f);
    float4 acc1 = make_float4(0.f,0.f,0.f,0.f);

    for (int j = s; j < e; j++) {
        int cj = g_cols[j];
        float vj = g_vals[j];
        const float4* __restrict__ base = (const float4*)(g_bufB + (size_t)cj * FP_ + fbase);
        float4 t0 = base[lane];
        float4 t1 = base[32 + lane];
        acc0.x = fmaf(vj, t0.x, acc0.x); acc0.y = fmaf(vj, t0.y, acc0.y);
        acc0.z = fmaf(vj, t0.z, acc0.z); acc0.w = fmaf(vj, t0.w, acc0.w);
        acc1.x = fmaf(vj, t1.x, acc1.x); acc1.y = fmaf(vj, t1.y, acc1.y);
        acc1.z = fmaf(vj, t1.z, acc1.z); acc1.w = fmaf(vj, t1.w, acc1.w);
    }

    float px = rpos[3*row+0], py = rpos[3*row+1], pz = rpos[3*row+2];
    float rx = px - rcpos[0], ry = py - rcpos[1], rz = pz - rcpos[2];
    float dr = sqrtf(rx*rx + ry*ry + rz*rz);
    float br = c_c32() * (dr * c_s32());
    float wamp = __expf(c_kdec() * dr) / (dr*dr + 0.001f);

    float sx, cx;
    sc_big(br * (float)(fbase + lane*2), sx, cx);
    float2 w0 = make_float2(cx, sx);
    sc_big(br * (float)(fbase + lane*2 + 1), sx, cx);
    float2 w1 = make_float2(cx, sx);
    sc_big(br * 64.0f, sx, cx);
    float2 wst = make_float2(cx, sx);

    float4* outp = (float4*)(g_bufA + (size_t)row*FP_ + fbase);
    {
        outp[lane] = acc0;
        float2 e0 = cmul(make_float2(acc0.x, acc0.y), w0);
        float2 e1 = cmul(make_float2(acc0.z, acc0.w), w1);
        *(float4*)&esh[w][lane*2] = make_float4(wamp*e0.x, wamp*e0.y, wamp*e1.x, wamp*e1.y);
        w0 = cmul(w0, wst); w1 = cmul(w1, wst);
        outp[32 + lane] = acc1;
        e0 = cmul(make_float2(acc1.x, acc1.y), w0);
        e1 = cmul(make_float2(acc1.z, acc1.w), w1);
        *(float4*)&esh[w][64 + lane*2] = make_float4(wamp*e0.x, wamp*e0.y, wamp*e1.x, wamp*e1.y);
    }
    __syncthreads();
    if (threadIdx.x < CH_) {
        int f = threadIdx.x;
        float sr = 0.0f, si = 0.0f;
#pragma unroll
        for (int ww = 0; ww < 8; ww++) { sr += esh[ww][f].x; si += esh[ww][f].y; }
        atomicAdd(&g_echo[2*(fbase + f)    ], sr);
        atomicAdd(&g_echo[2*(fbase + f) + 1], si);
    }
}

// f = 512 sparse step + echo (warp-reduced atomics)
__global__ void __launch_bounds__(256) k_spmm512(const float* __restrict__ rpos,
                                                 const float* __restrict__ rcpos) {
    int row = blockIdx.x * 256 + threadIdx.x;
    int lane = threadIdx.x & 31;
    int s = g_rowptr[row], e = g_rowptr[row+1];
    float ar = 0.0f, ai = 0.0f;
    for (int j = s; j < e; j++) {
        int cj = g_cols[j];
        float vj = g_vals[j];
        float2 t = g_bufB[(size_t)cj*FP_ + 512];
        ar = fmaf(vj, t.x, ar);
        ai = fmaf(vj, t.y, ai);
    }
    g_bufA[(size_t)row*FP_ + 512] = make_float2(ar, ai);

    float px = rpos[3*row+0], py = rpos[3*row+1], pz = rpos[3*row+2];
    float rx = px - rcpos[0], ry = py - rcpos[1], rz = pz - rcpos[2];
    float dr = sqrtf(rx*rx + ry*ry + rz*rz);
    float br = c_c32() * (dr * c_s32());
    float wamp = __expf(c_kdec() * dr) / (dr*dr + 0.001f);
    float ss, cc; sc_big(br * 512.0f, ss, cc);
    float er = wamp * (cc*ar - ss*ai);
    float ei = wamp * (cc*ai + ss*ar);
#pragma unroll
    for (int off = 16; off > 0; off >>= 1) {
        er += __shfl_down_sync(0xffffffffu, er, off);
        ei += __shfl_down_sync(0xffffffffu, ei, off);
    }
    if (lane == 0) {
        atomicAdd(&g_echo[1024], er);
        atomicAdd(&g_echo[1025], ei);
    }
}

// ---------------- final: irfft(echo) / fsm_window (+ rowcnt re-zero) ----------
__global__ void __launch_bounds__(1024) k_ifft() {
    __shared__ float twc[T_], tws[T_];
    __shared__ float2 es[32];
    int t = threadIdx.x, b = blockIdx.x;
    g_rowcnt[b*1024 + t] = 0;                 // restore replay invariant
    {
        float th = (float)(2.0*3.14159265358979323846/1024.0) * (float)t;
        float s, c; __sincosf(th, &s, &c);
        twc[t] = c; tws[t] = s;
    }
    if (t < 32) {
        int k = b*32 + 1 + t;
        float2 v = make_float2(g_echo[2*k], g_echo[2*k+1]);
        if (k == 512) { v.x *= 0.5f; v.y *= 0.5f; }
        es[t] = v;
    }
    __syncthreads();
    float sum = 0.0f;
#pragma unroll 8
    for (int i = 0; i < 32; i++) {
        int k = b*32 + 1 + i;
        int m = (k * t) & 1023;
        float2 X = es[i];
        sum = fmaf(2.0f * X.x, twc[m], sum);
        sum = fmaf(-2.0f * X.y, tws[m], sum);
    }
    atomicAdd(&g_time[t], sum);
}

__global__ void __launch_bounds__(1024) k_scale(float* __restrict__ out) {
    int t = threadIdx.x;
    float v = (g_time[t] + g_echo[0]) * (1.0f / 1024.0f);
    float ta = (float)t / 16000.0f;
    float fsm = __expf(LOG_GAMMA_F * ta);
    out[t] = v / fsm;
}

// ---------------- launcher ----------------------------------------------------
extern "C" void kernel_launch(void* const* d_in, const int* in_sizes, int n_in,
                              void* d_out, int out_size) {
    const float* spos  = (const float*)d_in[0];
    const float* rcpos = (const float*)d_in[1];
    const float* absorb= (const float*)d_in[2];
    const float* scat  = (const float*)d_in[3];
    const float* gkv   = (const float*)d_in[4];
    const float* basis = (const float*)d_in[5];
    const float* avg   = (const float*)d_in[6];
    const float* rpos  = (const float*)d_in[7];
    const int*   gkr   = (const int*)d_in[8];
    const int*   gkc   = (const int*)d_in[9];
    const int*   obj   = (const int*)d_in[10];

    k_setup<<<(P_*D_*D_)/256, 256>>>(basis, absorb, scat, obj, gkr);   // 1
    k_rad<<<R_/8, 256>>>(rpos, spos, rcpos);                           // 2
    k_scan<<<1, 1024>>>();                                             // 3
    k_gemm_tc<<<dim3(P_, 4), 512>>>(avg, 0);                           // 4  <- profile target (c0,b0)
    k_scatter<<<E_/256, 256>>>(gkr, gkc, gkv);                         // 5
    k_spmm<<<R_/8, 256>>>(rpos, rcpos, 0);                             // 6  (c0,b0)
    for (int b = 1; b < 4; b++) {                                      // chunk 0, bounces 1..3
        k_gemm_tc<<<dim3(P_, 4), 512>>>(avg, 0);
        k_spmm<<<R_/8, 256>>>(rpos, rcpos, 0);
    }
    for (int c = 1; c < 4; c++) {                                      // chunks 1..3, L2-resident
        for (int b = 0; b < 4; b++) {
            k_gemm_tc<<<dim3(P_, 4), 512>>>(avg, c*CH_);
            k_spmm<<<R_/8, 256>>>(rpos, rcpos, c*CH_);
        }
    }
    for (int b = 0; b < 4; b++) {                                      // f = 512 column
        k_gemm_last<<<P_, 128>>>(avg);
        k_spmm512<<<R_/256, 256>>>(rpos, rcpos);
    }
    k_ifft<<<16, 1024>>>();
    k_scale<<<1, 1024>>>((float*)d_out);
}

// round 15
// speedup vs baseline: 1.7955x; 1.7955x over previous
#include <cuda_runtime.h>
#include <cuda_bf16.h>
#include <cstdint>

#define P_  128
#define D_  128
#define R_  16384
#define E_  131072
#define T_  1024
#define F_  513
#define FP_ 520     // padded row stride in float2 (16B-aligned rows)

// ---------------- scratch (static device allocations; no cudaMalloc) ----------
static __device__ __align__(16) float2 g_bufA[R_*FP_ + 256];   // r_k
static __device__ __align__(16) float2 g_bufB[R_*FP_ + 256];   // prop * (K r)
static __device__ __align__(16) float  g_K[P_*D_*D_];          // [p][e][d] (f=512 path)
static __device__ __align__(16) uint4  g_AfragHi[P_*8*8*32];   // mma-fragment-ordered K (hi)
static __device__ __align__(16) uint4  g_AfragLo[P_*8*8*32];   // mma-fragment-ordered K (lo)
static __device__ __align__(16) int g_rowptr[R_+4];
static __device__ __align__(16) int g_rowcnt[R_];              // zeroed by k_ifft each call
static __device__ int    g_cols[E_];
static __device__ float  g_vals[E_];
static __device__ float  g_echo[2*F_];
static __device__ float  g_time[T_];

// ---------------- constants matching reference fp32 rounding ------------------
__device__ __forceinline__ float c_s32()  { return (float)(16000.0/343.0); }
__device__ __forceinline__ float c_c32()  { return (float)(-2.0*3.14159265358979323846/1024.0); }
__device__ __forceinline__ float c_kdec() { return (float)(-6.907755278982137/343.0 - 0.001); }
#define LOG_GAMMA_F (-6.907755278982137f)

__device__ __forceinline__ void sc_big(float x, float& s, float& c) {
    float k = rintf(x * 0.15915494309189535f);
    float r = fmaf(k, -6.28125f, x);
    r = fmaf(k, -1.9353071795864769e-3f, r);
    __sincosf(r, &s, &c);
}

__device__ __forceinline__ float2 cmul(float2 a, float2 b) {
    return make_float2(a.x*b.x - a.y*b.y, a.x*b.y + a.y*b.x);
}

__device__ __forceinline__ uint32_t smem_u32(const void* p) {
    uint32_t a;
    asm("{ .reg .u64 t; cvta.to.shared.u64 t, %1; cvt.u32.u64 %0, t; }" : "=r"(a) : "l"(p));
    return a;
}

__device__ __forceinline__ uint32_t pk_bf2(float a, float b) {
    __nv_bfloat16 ha = __float2bfloat16(a), hb = __float2bfloat16(b);
    return ((uint32_t)__bfloat16_as_ushort(hb) << 16) | __bfloat16_as_ushort(ha);
}
__device__ __forceinline__ uint32_t pk_bf2_lo(float a, float b) {
    __nv_bfloat16 ha = __float2bfloat16(a), hb = __float2bfloat16(b);
    float ra = a - __bfloat162float(ha);
    float rb = b - __bfloat162float(hb);
    __nv_bfloat16 la = __float2bfloat16(ra), lb = __float2bfloat16(rb);
    return ((uint32_t)__bfloat16_as_ushort(lb) << 16) | __bfloat16_as_ushort(la);
}

// base-ISA tensor ops (sm_80+/75+, valid in compute_103 PTX)
__device__ __forceinline__ void mma_bf16(float& d0, float& d1, float& d2, float& d3,
                                         uint32_t a0, uint32_t a1, uint32_t a2, uint32_t a3,
                                         uint32_t b0, uint32_t b1) {
    asm volatile("mma.sync.aligned.m16n8k16.row.col.f32.bf16.bf16.f32 "
                 "{%0,%1,%2,%3}, {%4,%5,%6,%7}, {%8,%9}, {%0,%1,%2,%3};"
                 : "+f"(d0), "+f"(d1), "+f"(d2), "+f"(d3)
                 : "r"(a0), "r"(a1), "r"(a2), "r"(a3), "r"(b0), "r"(b1));
}
__device__ __forceinline__ void ldsm_x4_t(uint32_t& r0, uint32_t& r1, uint32_t& r2, uint32_t& r3,
                                          uint32_t addr) {
    asm volatile("ldmatrix.sync.aligned.m8n8.x4.trans.shared.b16 {%0,%1,%2,%3}, [%4];"
                 : "=r"(r0), "=r"(r1), "=r"(r2), "=r"(r3) : "r"(addr));
}

// ---------------- fused setup: K (fp32 + mma frags), zeros, CSR hist ----------
__global__ void k_setup(const float* __restrict__ basis, const float* __restrict__ absorb,
                        const float* __restrict__ scat, const int* __restrict__ obj,
                        const int* __restrict__ gkr) {
    int idx = blockIdx.x * blockDim.x + threadIdx.x;
    if (idx < 2*F_) g_echo[idx] = 0.0f;
    if (idx < T_)   g_time[idx] = 0.0f;
    if (idx < E_)   atomicAdd(&g_rowcnt[gkr[idx]], 1);   // rowcnt pre-zeroed (static / k_ifft)

    if (idx < P_*8*8*32) {   // mma-fragment-ordered bf16 hi/lo A
        int lane = idx & 31;
        int dt = (idx >> 5) & 7;
        int s  = (idx >> 8) & 7;
        int p  = idx >> 11;
        int o = obj[p];
        float refl = 1.0f - absorb[o];
        float c0 = refl * scat[o];
        float c1 = refl * (1.0f - scat[o]);
        int r  = lane >> 2, cq = lane & 3;
        int d0 = dt*16 + r, d1 = d0 + 8;
        int k0 = s*16 + cq*2;
#define KV(d, e) (c0 * basis[(d)*D_ + (e)] + c1 * basis[D_*D_ + (d)*D_ + (e)])
        float v00 = KV(d0, k0),     v01 = KV(d0, k0+1);
        float v10 = KV(d1, k0),     v11 = KV(d1, k0+1);
        float v02 = KV(d0, k0+8),   v03 = KV(d0, k0+9);
        float v12 = KV(d1, k0+8),   v13 = KV(d1, k0+9);
        g_AfragHi[idx] = make_uint4(pk_bf2(v00,v01), pk_bf2(v10,v11),
                                    pk_bf2(v02,v03), pk_bf2(v12,v13));
        g_AfragLo[idx] = make_uint4(pk_bf2_lo(v00,v01), pk_bf2_lo(v10,v11),
                                    pk_bf2_lo(v02,v03), pk_bf2_lo(v12,v13));
    }

    if (idx >= P_*D_*D_) return;
    {   // fp32 K for the f=512 path
        int p = idx / (D_*D_);
        int rem = idx - p*D_*D_;
        int e = rem / D_;
        int d = rem - e*D_;
        int o = obj[p];
        float refl = 1.0f - absorb[o];
        float c0 = refl * scat[o];
        float c1 = refl * (1.0f - scat[o]);
        g_K[idx] = c0 * basis[d*D_ + e] + c1 * basis[D_*D_ + d*D_ + e];
#undef KV
    }
}

__global__ void __launch_bounds__(1024) k_scan() {
    __shared__ int wsum[32];
    int t = threadIdx.x, lane = t & 31, wid = t >> 5;
    int4 v[4];
    const int4* src = (const int4*)g_rowcnt;
#pragma unroll
    for (int i = 0; i < 4; i++) v[i] = src[t*4 + i];
    const int* x = (const int*)v;
    int loc[16], sum = 0;
#pragma unroll
    for (int i = 0; i < 16; i++) { loc[i] = sum; sum += x[i]; }
    int incl = sum;
#pragma unroll
    for (int off = 1; off < 32; off <<= 1) {
        int n = __shfl_up_sync(0xffffffffu, incl, off);
        if (lane >= off) incl += n;
    }
    if (lane == 31) wsum[wid] = incl;
    __syncthreads();
    if (wid == 0) {
        int ws = wsum[lane];
#pragma unroll
        for (int off = 1; off < 32; off <<= 1) {
            int n = __shfl_up_sync(0xffffffffu, ws, off);
            if (lane >= off) ws += n;
        }
        wsum[lane] = ws;
    }
    __syncthreads();
    int off0 = (wid > 0 ? wsum[wid-1] : 0) + (incl - sum);
    int4 o[4];
    int* op = (int*)o;
#pragma unroll
    for (int i = 0; i < 16; i++) op[i] = off0 + loc[i];
    int4* dst = (int4*)g_rowptr;
    int4* cz  = (int4*)g_rowcnt;
    int4 z = make_int4(0,0,0,0);
#pragma unroll
    for (int i = 0; i < 4; i++) { dst[t*4 + i] = o[i]; cz[t*4 + i] = z; }
    if (t == 1023) g_rowptr[R_] = wsum[31];
}

__global__ void k_scatter(const int* __restrict__ gkr, const int* __restrict__ gkc,
                          const float* __restrict__ gkv) {
    int e = blockIdx.x * blockDim.x + threadIdx.x;
    if (e >= E_) return;
    int r = gkr[e];
    int pos = g_rowptr[r] + atomicAdd(&g_rowcnt[r], 1);
    g_cols[pos] = gkc[e];
    g_vals[pos] = gkv[e];
}

// ---------------- rad: bufA = rad, echo += w_rec*pf_rec*rad -------------------
__global__ void __launch_bounds__(256) k_rad(const float* __restrict__ rpos,
                                             const float* __restrict__ spos,
                                             const float* __restrict__ rcpos) {
    __shared__ __align__(16) float2 esh[8][520];
    int w = threadIdx.x >> 5, lane = threadIdx.x & 31;
    int row = blockIdx.x * 8 + w;

    float px = rpos[3*row+0], py = rpos[3*row+1], pz = rpos[3*row+2];
    float dx = px - spos[0], dy = py - spos[1], dz = pz - spos[2];
    float ds = sqrtf(dx*dx + dy*dy + dz*dz);
    float bs = c_c32() * (ds * c_s32());
    float amp = __expf(c_kdec() * ds) / (ds*ds + 0.001f);

    float rx = px - rcpos[0], ry = py - rcpos[1], rz = pz - rcpos[2];
    float dr = sqrtf(rx*rx + ry*ry + rz*rz);
    float br = c_c32() * (dr * c_s32());
    float wamp = __expf(c_kdec() * dr) / (dr*dr + 0.001f);

    float s0, c0;
    sc_big(bs * (float)lane, s0, c0);
    float2 wsrc = make_float2(c0, s0);
    sc_big(bs * 32.0f, s0, c0);
    float2 wsstep = make_float2(c0, s0);
    sc_big(br * (float)lane, s0, c0);
    float2 wrec = make_float2(c0, s0);
    sc_big(br * 32.0f, s0, c0);
    float2 wrstep = make_float2(c0, s0);

#pragma unroll
    for (int k = 0; k < 16; k++) {
        int f = k*32 + lane;
        float2 rad = make_float2(amp * wsrc.x, amp * wsrc.y);
        g_bufA[(size_t)row*FP_ + f] = rad;
        float2 er = cmul(rad, wrec);
        esh[w][f] = make_float2(wamp * er.x, wamp * er.y);
        wsrc = cmul(wsrc, wsstep);
        wrec = cmul(wrec, wrstep);
    }
    if (lane == 0) {
        float2 rad = make_float2(amp * wsrc.x, amp * wsrc.y);
        g_bufA[(size_t)row*FP_ + 512] = rad;
        float2 er = cmul(rad, wrec);
        esh[w][512] = make_float2(wamp * er.x, wamp * er.y);
    }
    __syncthreads();
    for (int f = threadIdx.x; f < F_; f += 256) {
        float sr = 0.0f, si = 0.0f;
#pragma unroll
        for (int ww = 0; ww < 8; ww++) { sr += esh[ww][f].x; si += esh[ww][f].y; }
        atomicAdd(&g_echo[2*f  ], sr);
        atomicAdd(&g_echo[2*f+1], si);
    }
}

// ---------------- tensor GEMM (mma.sync bf16-split): bufB = prop*(K_p @ bufA) -
// grid (P_, 16), 512 thr, 2 blocks/SM (32 warps). Block: D[128d x 64n].
// Warps: 8 along d x 2 along n; warp tile 16d x 32n. acc = 16 floats/thread.
#define BP_ 144   // B row pitch bytes (72 bf16) — conflict-free STS.128 + ldmatrix
__global__ void __launch_bounds__(512, 2) k_gemm_tc(const float* __restrict__ avg_dist) {
    __shared__ __align__(16) unsigned char Bhi[128*BP_];
    __shared__ __align__(16) unsigned char Blo[128*BP_];
    int p = blockIdx.x, ft = blockIdx.y, f0 = ft*32;
    int tid = threadIdx.x, w = tid >> 5, lane = tid & 31;
    int wd = w & 7, wn = w >> 3;

    // ---- stage B: thread owns (k = tid/4, quarter = tid&3) -> 16 n values
    {
        int k = tid >> 2, q = tid & 3;
        const float4* src = (const float4*)(g_bufA + (size_t)(p*128 + k)*FP_ + f0) + q*4;
        uint32_t hi[8], lo[8];
#pragma unroll
        for (int j = 0; j < 4; j++) {
            float4 v = src[j];
            hi[2*j]   = pk_bf2(v.x, v.y);
            hi[2*j+1] = pk_bf2(v.z, v.w);
            lo[2*j]   = pk_bf2_lo(v.x, v.y);
            lo[2*j+1] = pk_bf2_lo(v.z, v.w);
        }
        uint4* dh = (uint4*)(Bhi + k*BP_ + q*32);
        uint4* dl = (uint4*)(Blo + k*BP_ + q*32);
        dh[0] = make_uint4(hi[0], hi[1], hi[2], hi[3]);
        dh[1] = make_uint4(hi[4], hi[5], hi[6], hi[7]);
        dl[0] = make_uint4(lo[0], lo[1], lo[2], lo[3]);
        dl[1] = make_uint4(lo[4], lo[5], lo[6], lo[7]);
    }
    __syncthreads();

    float acc[4][4];
#pragma unroll
    for (int j = 0; j < 4; j++)
#pragma unroll
        for (int q = 0; q < 4; q++) acc[j][q] = 0.0f;

    // ldmatrix lane addresses: matrix g = lane/8 -> (k +8 if g&1, n +8 if g>>1)
    int g = lane >> 3, lr = lane & 7;
    uint32_t rowoff = (uint32_t)(((g & 1)*8 + lr) * BP_);
    uint32_t bs_hi = smem_u32(Bhi), bs_lo = smem_u32(Blo);
    uint32_t co0 = bs_hi + rowoff + (uint32_t)((wn*32 +  0 + (g >> 1)*8) * 2);
    uint32_t co1 = bs_hi + rowoff + (uint32_t)((wn*32 + 16 + (g >> 1)*8) * 2);
    uint32_t cl0 = bs_lo + rowoff + (uint32_t)((wn*32 +  0 + (g >> 1)*8) * 2);
    uint32_t cl1 = bs_lo + rowoff + (uint32_t)((wn*32 + 16 + (g >> 1)*8) * 2);

    const uint4* Ah = g_AfragHi + ((size_t)p * 8) * 8 * 32;
    const uint4* Al = g_AfragLo + ((size_t)p * 8) * 8 * 32;

#pragma unroll
    for (int s = 0; s < 8; s++) {
        uint4 ah = Ah[((s*8) + wd)*32 + lane];
        uint4 al = Al[((s*8) + wd)*32 + lane];
        uint32_t soff = (uint32_t)(s * 16 * BP_);
        uint32_t bh[8], bl[8];
        ldsm_x4_t(bh[0], bh[1], bh[2], bh[3], co0 + soff);
        ldsm_x4_t(bh[4], bh[5], bh[6], bh[7], co1 + soff);
        ldsm_x4_t(bl[0], bl[1], bl[2], bl[3], cl0 + soff);
        ldsm_x4_t(bl[4], bl[5], bl[6], bl[7], cl1 + soff);
#pragma unroll
        for (int nt = 0; nt < 4; nt++) {
            mma_bf16(acc[nt][0], acc[nt][1], acc[nt][2], acc[nt][3],
                     ah.x, ah.y, ah.z, ah.w, bh[2*nt], bh[2*nt+1]);
            mma_bf16(acc[nt][0], acc[nt][1], acc[nt][2], acc[nt][3],
                     ah.x, ah.y, ah.z, ah.w, bl[2*nt], bl[2*nt+1]);
            mma_bf16(acc[nt][0], acc[nt][1], acc[nt][2], acc[nt][3],
                     al.x, al.y, al.z, al.w, bh[2*nt], bh[2*nt+1]);
        }
    }

    // ---- epilogue with phase recurrence (stride 4 in f per nt step)
    int r0 = lane >> 2, fq = lane & 3;
#pragma unroll
    for (int half = 0; half < 2; half++) {
        int d = wd*16 + half*8 + r0;
        int row = p*128 + d;
        float dist = avg_dist[row];
        float b = c_c32() * (dist * c_s32());
        float dec = __expf(c_kdec() * dist);
        float2* outp = g_bufB + (size_t)row*FP_ + f0 + wn*16;
        int fbase = f0 + wn*16 + fq;
        float ss, cc;
        sc_big(b * (float)fbase, ss, cc);
        float2 wp = make_float2(dec * cc, dec * ss);
        sc_big(b * 4.0f, ss, cc);
        float2 wst = make_float2(cc, ss);
#pragma unroll
        for (int nt = 0; nt < 4; nt++) {
            float2 v = cmul(make_float2(acc[nt][half*2 + 0], acc[nt][half*2 + 1]), wp);
            outp[nt*4 + fq] = v;
            wp = cmul(wp, wst);
        }
    }
}

// f = 512 column only (fp32 path)
__global__ void __launch_bounds__(128) k_gemm_last(const float* __restrict__ avg_dist) {
    __shared__ float2 xs[128];
    int p = blockIdx.x, d = threadIdx.x;
    xs[d] = g_bufA[(size_t)(p*128 + d)*FP_ + 512];
    __syncthreads();
    const float* Kp = g_K + (size_t)p * D_ * D_;
    float ar = 0.0f, ai = 0.0f;
#pragma unroll 8
    for (int e = 0; e < 128; e++) {
        float kv = Kp[e*128 + d];
        float2 x = xs[e];
        ar = fmaf(kv, x.x, ar);
        ai = fmaf(kv, x.y, ai);
    }
    int row = p*128 + d;
    float dist = avg_dist[row];
    float b = c_c32() * (dist * c_s32());
    float dec = __expf(c_kdec() * dist);
    float ss, cc; sc_big(b * 512.0f, ss, cc);
    float pr = dec * cc, pi = dec * ss;
    g_bufB[(size_t)row*FP_ + 512] = make_float2(pr*ar - pi*ai, pr*ai + pi*ar);
}

// ---------------- SpMM: bufA = A @ bufB, echo += w_rec*pf_rec*bufA ------------
// edge-outer float4 gathers; echo epilogue uses phase recurrence (stride 64).
__global__ void __launch_bounds__(256) k_spmm(const float* __restrict__ rpos,
                                              const float* __restrict__ rcpos) {
    __shared__ __align__(16) float2 esh[8][520];
    int w = threadIdx.x >> 5, lane = threadIdx.x & 31;
    int row = blockIdx.x * 8 + w;
    int s = g_rowptr[row], e = g_rowptr[row+1];

    float4 acc[8];
#pragma unroll
    for (int k = 0; k < 8; k++) acc[k] = make_float4(0.f, 0.f, 0.f, 0.f);
    float ar16 = 0.0f, ai16 = 0.0f;

    for (int j = s; j < e; j++) {
        int cj = g_cols[j];
        float vj = g_vals[j];
        const float4* __restrict__ base = (const float4*)(g_bufB + (size_t)cj * FP_);
#pragma unroll
        for (int k = 0; k < 8; k++) {
            float4 t = base[k*32 + lane];
            acc[k].x = fmaf(vj, t.x, acc[k].x);
            acc[k].y = fmaf(vj, t.y, acc[k].y);
            acc[k].z = fmaf(vj, t.z, acc[k].z);
            acc[k].w = fmaf(vj, t.w, acc[k].w);
        }
        if (lane == 0) {
            float2 t = g_bufB[(size_t)cj*FP_ + 512];
            ar16 = fmaf(vj, t.x, ar16);
            ai16 = fmaf(vj, t.y, ai16);
        }
    }

    float px = rpos[3*row+0], py = rpos[3*row+1], pz = rpos[3*row+2];
    float rx = px - rcpos[0], ry = py - rcpos[1], rz = pz - rcpos[2];
    float dr = sqrtf(rx*rx + ry*ry + rz*rz);
    float br = c_c32() * (dr * c_s32());
    float wamp = __expf(c_kdec() * dr) / (dr*dr + 0.001f);

    float sx, cx;
    sc_big(br * (float)(lane*2), sx, cx);
    float2 w0 = make_float2(cx, sx);
    sc_big(br * (float)(lane*2 + 1), sx, cx);
    float2 w1 = make_float2(cx, sx);
    sc_big(br * 64.0f, sx, cx);
    float2 wst = make_float2(cx, sx);

    float4* outp = (float4*)(g_bufA + (size_t)row*FP_);
#pragma unroll
    for (int k = 0; k < 8; k++) {
        int f = k*64 + lane*2;
        outp[k*32 + lane] = acc[k];
        float2 e0 = cmul(make_float2(acc[k].x, acc[k].y), w0);
        float2 e1 = cmul(make_float2(acc[k].z, acc[k].w), w1);
        *(float4*)&esh[w][f] = make_float4(wamp*e0.x, wamp*e0.y, wamp*e1.x, wamp*e1.y);
        w0 = cmul(w0, wst);
        w1 = cmul(w1, wst);
    }
    // after 8 steps: w0 = e^{i br (lane*2 + 512)} -> lane 0 = f 512
    if (lane == 0) {
        g_bufA[(size_t)row*FP_ + 512] = make_float2(ar16, ai16);
        float2 e0 = cmul(make_float2(ar16, ai16), w0);
        esh[w][512] = make_float2(wamp*e0.x, wamp*e0.y);
    }
    __syncthreads();
    for (int f = threadIdx.x; f < F_; f += 256) {
        float sr = 0.0f, si = 0.0f;
#pragma unroll
        for (int ww = 0; ww < 8; ww++) { sr += esh[ww][f].x; si += esh[ww][f].y; }
        atomicAdd(&g_echo[2*f  ], sr);
        atomicAdd(&g_echo[2*f+1], si);
    }
}

// ---------------- final: irfft(echo) / fsm_window (+ rowcnt re-zero) ----------
__global__ void __launch_bounds__(1024) k_ifft() {
    __shared__ float twc[T_], tws[T_];
    __shared__ float2 es[32];
    int t = threadIdx.x, b = blockIdx.x;
    g_rowcnt[b*1024 + t] = 0;                 // restore replay invariant
    {
        float th = (float)(2.0*3.14159265358979323846/1024.0) * (float)t;
        float s, c; __sincosf(th, &s, &c);
        twc[t] = c; tws[t] = s;
    }
    if (t < 32) {
        int k = b*32 + 1 + t;
        float2 v = make_float2(g_echo[2*k], g_echo[2*k+1]);
        if (k == 512) { v.x *= 0.5f; v.y *= 0.5f; }
        es[t] = v;
    }
    __syncthreads();
    float sum = 0.0f;
#pragma unroll 8
    for (int i = 0; i < 32; i++) {
        int k = b*32 + 1 + i;
        int m = (k * t) & 1023;
        float2 X = es[i];
        sum = fmaf(2.0f * X.x, twc[m], sum);
        sum = fmaf(-2.0f * X.y, tws[m], sum);
    }
    atomicAdd(&g_time[t], sum);
}

__global__ void __launch_bounds__(1024) k_scale(float* __restrict__ out) {
    int t = threadIdx.x;
    float v = (g_time[t] + g_echo[0]) * (1.0f / 1024.0f);
    float ta = (float)t / 16000.0f;
    float fsm = __expf(LOG_GAMMA_F * ta);
    out[t] = v / fsm;
}

// ---------------- launcher ----------------------------------------------------
extern "C" void kernel_launch(void* const* d_in, const int* in_sizes, int n_in,
                              void* d_out, int out_size) {
    const float* spos  = (const float*)d_in[0];
    const float* rcpos = (const float*)d_in[1];
    const float* absorb= (const float*)d_in[2];
    const float* scat  = (const float*)d_in[3];
    const float* gkv   = (const float*)d_in[4];
    const float* basis = (const float*)d_in[5];
    const float* avg   = (const float*)d_in[6];
    const float* rpos  = (const float*)d_in[7];
    const int*   gkr   = (const int*)d_in[8];
    const int*   gkc   = (const int*)d_in[9];
    const int*   obj   = (const int*)d_in[10];

    k_setup<<<(P_*D_*D_)/256, 256>>>(basis, absorb, scat, obj, gkr);   // 1
    k_rad<<<R_/8, 256>>>(rpos, spos, rcpos);                           // 2
    k_scan<<<1, 1024>>>();                                             // 3
    k_gemm_tc<<<dim3(P_, 16), 512>>>(avg);                             // 4  <- profile target
    k_scatter<<<E_/256, 256>>>(gkr, gkc, gkv);                         // 5
    k_gemm_last<<<P_, 128>>>(avg);                                     // 6
    k_spmm<<<R_/8, 256>>>(rpos, rcpos);                                // 7
    for (int b = 1; b < 4; b++) {
        k_gemm_tc<<<dim3(P_, 16), 512>>>(avg);
        k_gemm_last<<<P_, 128>>>(avg);
        k_spmm<<<R_/8, 256>>>(rpos, rcpos);
    }
    k_ifft<<<16, 1024>>>();
    k_scale<<<1, 1024>>>((float*)d_out);
}

// round 16
// speedup vs baseline: 1.8330x; 1.0209x over previous
#include <cuda_runtime.h>
#include <cuda_bf16.h>
#include <cstdint>

#define P_  128
#define D_  128
#define R_  16384
#define E_  131072
#define T_  1024
#define F_  513
#define FP_ 520     // padded row stride in float2 (16B-aligned rows)

// ---------------- scratch (static device allocations; no cudaMalloc) ----------
static __device__ __align__(16) float2 g_bufA[R_*FP_ + 256];   // r_k (single-use: stream)
static __device__ __align__(16) float2 g_bufB[R_*FP_ + 256];   // prop*(K r) (8x reuse: cache)
static __device__ __align__(16) float  g_K[P_*D_*D_];          // [p][e][d] (f=512 path)
static __device__ __align__(16) uint4  g_AfragHi[P_*8*8*32];   // mma-fragment-ordered K (hi)
static __device__ __align__(16) uint4  g_AfragLo[P_*8*8*32];   // mma-fragment-ordered K (lo)
static __device__ __align__(16) int g_rowptr[R_+4];
static __device__ __align__(16) int g_rowcnt[R_];              // zeroed by k_ifft each call
static __device__ int    g_cols[E_];
static __device__ float  g_vals[E_];
static __device__ float  g_echo[2*F_];
static __device__ float  g_time[T_];

// ---------------- constants matching reference fp32 rounding ------------------
__device__ __forceinline__ float c_s32()  { return (float)(16000.0/343.0); }
__device__ __forceinline__ float c_c32()  { return (float)(-2.0*3.14159265358979323846/1024.0); }
__device__ __forceinline__ float c_kdec() { return (float)(-6.907755278982137/343.0 - 0.001); }
#define LOG_GAMMA_F (-6.907755278982137f)

__device__ __forceinline__ void sc_big(float x, float& s, float& c) {
    float k = rintf(x * 0.15915494309189535f);
    float r = fmaf(k, -6.28125f, x);
    r = fmaf(k, -1.9353071795864769e-3f, r);
    __sincosf(r, &s, &c);
}

__device__ __forceinline__ float2 cmul(float2 a, float2 b) {
    return make_float2(a.x*b.x - a.y*b.y, a.x*b.y + a.y*b.x);
}

__device__ __forceinline__ uint32_t smem_u32(const void* p) {
    uint32_t a;
    asm("{ .reg .u64 t; cvta.to.shared.u64 t, %1; cvt.u32.u64 %0, t; }" : "=r"(a) : "l"(p));
    return a;
}

__device__ __forceinline__ uint32_t pk_bf2(float a, float b) {
    __nv_bfloat16 ha = __float2bfloat16(a), hb = __float2bfloat16(b);
    return ((uint32_t)__bfloat16_as_ushort(hb) << 16) | __bfloat16_as_ushort(ha);
}
__device__ __forceinline__ uint32_t pk_bf2_lo(float a, float b) {
    __nv_bfloat16 ha = __float2bfloat16(a), hb = __float2bfloat16(b);
    float ra = a - __bfloat162float(ha);
    float rb = b - __bfloat162float(hb);
    __nv_bfloat16 la = __float2bfloat16(ra), lb = __float2bfloat16(rb);
    return ((uint32_t)__bfloat16_as_ushort(lb) << 16) | __bfloat16_as_ushort(la);
}

// base-ISA tensor ops (sm_80+/75+, valid in compute_103 PTX)
__device__ __forceinline__ void mma_bf16(float& d0, float& d1, float& d2, float& d3,
                                         uint32_t a0, uint32_t a1, uint32_t a2, uint32_t a3,
                                         uint32_t b0, uint32_t b1) {
    asm volatile("mma.sync.aligned.m16n8k16.row.col.f32.bf16.bf16.f32 "
                 "{%0,%1,%2,%3}, {%4,%5,%6,%7}, {%8,%9}, {%0,%1,%2,%3};"
                 : "+f"(d0), "+f"(d1), "+f"(d2), "+f"(d3)
                 : "r"(a0), "r"(a1), "r"(a2), "r"(a3), "r"(b0), "r"(b1));
}
__device__ __forceinline__ void ldsm_x4_t(uint32_t& r0, uint32_t& r1, uint32_t& r2, uint32_t& r3,
                                          uint32_t addr) {
    asm volatile("ldmatrix.sync.aligned.m8n8.x4.trans.shared.b16 {%0,%1,%2,%3}, [%4];"
                 : "=r"(r0), "=r"(r1), "=r"(r2), "=r"(r3) : "r"(addr));
}

// ---------------- fused setup: K (fp32 + mma frags), zeros, CSR hist ----------
__global__ void k_setup(const float* __restrict__ basis, const float* __restrict__ absorb,
                        const float* __restrict__ scat, const int* __restrict__ obj,
                        const int* __restrict__ gkr) {
    int idx = blockIdx.x * blockDim.x + threadIdx.x;
    if (idx < 2*F_) g_echo[idx] = 0.0f;
    if (idx < T_)   g_time[idx] = 0.0f;
    if (idx < E_)   atomicAdd(&g_rowcnt[gkr[idx]], 1);   // rowcnt pre-zeroed (static / k_ifft)

    if (idx < P_*8*8*32) {   // mma-fragment-ordered bf16 hi/lo A
        int lane = idx & 31;
        int dt = (idx >> 5) & 7;
        int s  = (idx >> 8) & 7;
        int p  = idx >> 11;
        int o = obj[p];
        float refl = 1.0f - absorb[o];
        float c0 = refl * scat[o];
        float c1 = refl * (1.0f - scat[o]);
        int r  = lane >> 2, cq = lane & 3;
        int d0 = dt*16 + r, d1 = d0 + 8;
        int k0 = s*16 + cq*2;
#define KV(d, e) (c0 * basis[(d)*D_ + (e)] + c1 * basis[D_*D_ + (d)*D_ + (e)])
        float v00 = KV(d0, k0),     v01 = KV(d0, k0+1);
        float v10 = KV(d1, k0),     v11 = KV(d1, k0+1);
        float v02 = KV(d0, k0+8),   v03 = KV(d0, k0+9);
        float v12 = KV(d1, k0+8),   v13 = KV(d1, k0+9);
        g_AfragHi[idx] = make_uint4(pk_bf2(v00,v01), pk_bf2(v10,v11),
                                    pk_bf2(v02,v03), pk_bf2(v12,v13));
        g_AfragLo[idx] = make_uint4(pk_bf2_lo(v00,v01), pk_bf2_lo(v10,v11),
                                    pk_bf2_lo(v02,v03), pk_bf2_lo(v12,v13));
    }

    if (idx >= P_*D_*D_) return;
    {   // fp32 K for the f=512 path
        int p = idx / (D_*D_);
        int rem = idx - p*D_*D_;
        int e = rem / D_;
        int d = rem - e*D_;
        int o = obj[p];
        float refl = 1.0f - absorb[o];
        float c0 = refl * scat[o];
        float c1 = refl * (1.0f - scat[o]);
        g_K[idx] = c0 * basis[d*D_ + e] + c1 * basis[D_*D_ + d*D_ + e];
#undef KV
    }
}

__global__ void __launch_bounds__(1024) k_scan() {
    __shared__ int wsum[32];
    int t = threadIdx.x, lane = t & 31, wid = t >> 5;
    int4 v[4];
    const int4* src = (const int4*)g_rowcnt;
#pragma unroll
    for (int i = 0; i < 4; i++) v[i] = src[t*4 + i];
    const int* x = (const int*)v;
    int loc[16], sum = 0;
#pragma unroll
    for (int i = 0; i < 16; i++) { loc[i] = sum; sum += x[i]; }
    int incl = sum;
#pragma unroll
    for (int off = 1; off < 32; off <<= 1) {
        int n = __shfl_up_sync(0xffffffffu, incl, off);
        if (lane >= off) incl += n;
    }
    if (lane == 31) wsum[wid] = incl;
    __syncthreads();
    if (wid == 0) {
        int ws = wsum[lane];
#pragma unroll
        for (int off = 1; off < 32; off <<= 1) {
            int n = __shfl_up_sync(0xffffffffu, ws, off);
            if (lane >= off) ws += n;
        }
        wsum[lane] = ws;
    }
    __syncthreads();
    int off0 = (wid > 0 ? wsum[wid-1] : 0) + (incl - sum);
    int4 o[4];
    int* op = (int*)o;
#pragma unroll
    for (int i = 0; i < 16; i++) op[i] = off0 + loc[i];
    int4* dst = (int4*)g_rowptr;
    int4* cz  = (int4*)g_rowcnt;
    int4 z = make_int4(0,0,0,0);
#pragma unroll
    for (int i = 0; i < 4; i++) { dst[t*4 + i] = o[i]; cz[t*4 + i] = z; }
    if (t == 1023) g_rowptr[R_] = wsum[31];
}

__global__ void k_scatter(const int* __restrict__ gkr, const int* __restrict__ gkc,
                          const float* __restrict__ gkv) {
    int e = blockIdx.x * blockDim.x + threadIdx.x;
    if (e >= E_) return;
    int r = gkr[e];
    int pos = g_rowptr[r] + atomicAdd(&g_rowcnt[r], 1);
    g_cols[pos] = gkc[e];
    g_vals[pos] = gkv[e];
}

// ---------------- rad: bufA = rad, echo += w_rec*pf_rec*rad -------------------
__global__ void __launch_bounds__(256) k_rad(const float* __restrict__ rpos,
                                             const float* __restrict__ spos,
                                             const float* __restrict__ rcpos) {
    __shared__ __align__(16) float2 esh[8][520];
    int w = threadIdx.x >> 5, lane = threadIdx.x & 31;
    int row = blockIdx.x * 8 + w;

    float px = rpos[3*row+0], py = rpos[3*row+1], pz = rpos[3*row+2];
    float dx = px - spos[0], dy = py - spos[1], dz = pz - spos[2];
    float ds = sqrtf(dx*dx + dy*dy + dz*dz);
    float bs = c_c32() * (ds * c_s32());
    float amp = __expf(c_kdec() * ds) / (ds*ds + 0.001f);

    float rx = px - rcpos[0], ry = py - rcpos[1], rz = pz - rcpos[2];
    float dr = sqrtf(rx*rx + ry*ry + rz*rz);
    float br = c_c32() * (dr * c_s32());
    float wamp = __expf(c_kdec() * dr) / (dr*dr + 0.001f);

    float s0, c0;
    sc_big(bs * (float)lane, s0, c0);
    float2 wsrc = make_float2(c0, s0);
    sc_big(bs * 32.0f, s0, c0);
    float2 wsstep = make_float2(c0, s0);
    sc_big(br * (float)lane, s0, c0);
    float2 wrec = make_float2(c0, s0);
    sc_big(br * 32.0f, s0, c0);
    float2 wrstep = make_float2(c0, s0);

#pragma unroll
    for (int k = 0; k < 16; k++) {
        int f = k*32 + lane;
        float2 rad = make_float2(amp * wsrc.x, amp * wsrc.y);
        __stcs(&g_bufA[(size_t)row*FP_ + f], rad);
        float2 er = cmul(rad, wrec);
        esh[w][f] = make_float2(wamp * er.x, wamp * er.y);
        wsrc = cmul(wsrc, wsstep);
        wrec = cmul(wrec, wrstep);
    }
    if (lane == 0) {
        float2 rad = make_float2(amp * wsrc.x, amp * wsrc.y);
        __stcs(&g_bufA[(size_t)row*FP_ + 512], rad);
        float2 er = cmul(rad, wrec);
        esh[w][512] = make_float2(wamp * er.x, wamp * er.y);
    }
    __syncthreads();
    for (int f = threadIdx.x; f < F_; f += 256) {
        float sr = 0.0f, si = 0.0f;
#pragma unroll
        for (int ww = 0; ww < 8; ww++) { sr += esh[ww][f].x; si += esh[ww][f].y; }
        atomicAdd(&g_echo[2*f  ], sr);
        atomicAdd(&g_echo[2*f+1], si);
    }
}

// ---------------- tensor GEMM (mma.sync bf16-split): bufB = prop*(K_p @ bufA) -
// grid (P_, 16), 512 thr, 2 blocks/SM (32 warps). Block: D[128d x 64n].
// Warps: 8 along d x 2 along n; warp tile 16d x 32n. acc = 16 floats/thread.
#define BP_ 144   // B row pitch bytes (72 bf16) — conflict-free STS.128 + ldmatrix
__global__ void __launch_bounds__(512, 2) k_gemm_tc(const float* __restrict__ avg_dist) {
    __shared__ __align__(16) unsigned char Bhi[128*BP_];
    __shared__ __align__(16) unsigned char Blo[128*BP_];
    int p = blockIdx.x, ft = blockIdx.y, f0 = ft*32;
    int tid = threadIdx.x, w = tid >> 5, lane = tid & 31;
    int wd = w & 7, wn = w >> 3;

    // ---- stage B: thread owns (k = tid/4, quarter = tid&3) -> 16 n values
    // bufA is single-use here: stream (evict-first) so bufB stays L2-resident.
    {
        int k = tid >> 2, q = tid & 3;
        const float4* src = (const float4*)(g_bufA + (size_t)(p*128 + k)*FP_ + f0) + q*4;
        uint32_t hi[8], lo[8];
#pragma unroll
        for (int j = 0; j < 4; j++) {
            float4 v = __ldcs(src + j);
            hi[2*j]   = pk_bf2(v.x, v.y);
            hi[2*j+1] = pk_bf2(v.z, v.w);
            lo[2*j]   = pk_bf2_lo(v.x, v.y);
            lo[2*j+1] = pk_bf2_lo(v.z, v.w);
        }
        uint4* dh = (uint4*)(Bhi + k*BP_ + q*32);
        uint4* dl = (uint4*)(Blo + k*BP_ + q*32);
        dh[0] = make_uint4(hi[0], hi[1], hi[2], hi[3]);
        dh[1] = make_uint4(hi[4], hi[5], hi[6], hi[7]);
        dl[0] = make_uint4(lo[0], lo[1], lo[2], lo[3]);
        dl[1] = make_uint4(lo[4], lo[5], lo[6], lo[7]);
    }
    __syncthreads();

    float acc[4][4];
#pragma unroll
    for (int j = 0; j < 4; j++)
#pragma unroll
        for (int q = 0; q < 4; q++) acc[j][q] = 0.0f;

    // ldmatrix lane addresses: matrix g = lane/8 -> (k +8 if g&1, n +8 if g>>1)
    int g = lane >> 3, lr = lane & 7;
    uint32_t rowoff = (uint32_t)(((g & 1)*8 + lr) * BP_);
    uint32_t bs_hi = smem_u32(Bhi), bs_lo = smem_u32(Blo);
    uint32_t co0 = bs_hi + rowoff + (uint32_t)((wn*32 +  0 + (g >> 1)*8) * 2);
    uint32_t co1 = bs_hi + rowoff + (uint32_t)((wn*32 + 16 + (g >> 1)*8) * 2);
    uint32_t cl0 = bs_lo + rowoff + (uint32_t)((wn*32 +  0 + (g >> 1)*8) * 2);
    uint32_t cl1 = bs_lo + rowoff + (uint32_t)((wn*32 + 16 + (g >> 1)*8) * 2);

    const uint4* Ah = g_AfragHi + ((size_t)p * 8) * 8 * 32;
    const uint4* Al = g_AfragLo + ((size_t)p * 8) * 8 * 32;

#pragma unroll
    for (int s = 0; s < 8; s++) {
        uint4 ah = Ah[((s*8) + wd)*32 + lane];
        uint4 al = Al[((s*8) + wd)*32 + lane];
        uint32_t soff = (uint32_t)(s * 16 * BP_);
        uint32_t bh[8], bl[8];
        ldsm_x4_t(bh[0], bh[1], bh[2], bh[3], co0 + soff);
        ldsm_x4_t(bh[4], bh[5], bh[6], bh[7], co1 + soff);
        ldsm_x4_t(bl[0], bl[1], bl[2], bl[3], cl0 + soff);
        ldsm_x4_t(bl[4], bl[5], bl[6], bl[7], cl1 + soff);
#pragma unroll
        for (int nt = 0; nt < 4; nt++) {
            mma_bf16(acc[nt][0], acc[nt][1], acc[nt][2], acc[nt][3],
                     ah.x, ah.y, ah.z, ah.w, bh[2*nt], bh[2*nt+1]);
            mma_bf16(acc[nt][0], acc[nt][1], acc[nt][2], acc[nt][3],
                     ah.x, ah.y, ah.z, ah.w, bl[2*nt], bl[2*nt+1]);
            mma_bf16(acc[nt][0], acc[nt][1], acc[nt][2], acc[nt][3],
                     al.x, al.y, al.z, al.w, bh[2*nt], bh[2*nt+1]);
        }
    }

    // ---- epilogue with phase recurrence (stride 4 in f per nt step)
    int r0 = lane >> 2, fq = lane & 3;
#pragma unroll
    for (int half = 0; half < 2; half++) {
        int d = wd*16 + half*8 + r0;
        int row = p*128 + d;
        float dist = avg_dist[row];
        float b = c_c32() * (dist * c_s32());
        float dec = __expf(c_kdec() * dist);
        float2* outp = g_bufB + (size_t)row*FP_ + f0 + wn*16;
        int fbase = f0 + wn*16 + fq;
        float ss, cc;
        sc_big(b * (float)fbase, ss, cc);
        float2 wp = make_float2(dec * cc, dec * ss);
        sc_big(b * 4.0f, ss, cc);
        float2 wst = make_float2(cc, ss);
#pragma unroll
        for (int nt = 0; nt < 4; nt++) {
            float2 v = cmul(make_float2(acc[nt][half*2 + 0], acc[nt][half*2 + 1]), wp);
            outp[nt*4 + fq] = v;
            wp = cmul(wp, wst);
        }
    }
}

// f = 512 column only (fp32 path)
__global__ void __launch_bounds__(128) k_gemm_last(const float* __restrict__ avg_dist) {
    __shared__ float2 xs[128];
    int p = blockIdx.x, d = threadIdx.x;
    xs[d] = __ldcs(&g_bufA[(size_t)(p*128 + d)*FP_ + 512]);
    __syncthreads();
    const float* Kp = g_K + (size_t)p * D_ * D_;
    float ar = 0.0f, ai = 0.0f;
#pragma unroll 8
    for (int e = 0; e < 128; e++) {
        float kv = Kp[e*128 + d];
        float2 x = xs[e];
        ar = fmaf(kv, x.x, ar);
        ai = fmaf(kv, x.y, ai);
    }
    int row = p*128 + d;
    float dist = avg_dist[row];
    float b = c_c32() * (dist * c_s32());
    float dec = __expf(c_kdec() * dist);
    float ss, cc; sc_big(b * 512.0f, ss, cc);
    float pr = dec * cc, pi = dec * ss;
    g_bufB[(size_t)row*FP_ + 512] = make_float2(pr*ar - pi*ai, pr*ai + pi*ar);
}

// ---------------- SpMM: bufA = A @ bufB, echo += w_rec*pf_rec*bufA ------------
// edge-outer float4 gathers (bufB: cached, 8x reuse); bufA written streaming.
__global__ void __launch_bounds__(256) k_spmm(const float* __restrict__ rpos,
                                              const float* __restrict__ rcpos) {
    __shared__ __align__(16) float2 esh[8][520];
    int w = threadIdx.x >> 5, lane = threadIdx.x & 31;
    int row = blockIdx.x * 8 + w;
    int s = g_rowptr[row], e = g_rowptr[row+1];

    float4 acc[8];
#pragma unroll
    for (int k = 0; k < 8; k++) acc[k] = make_float4(0.f, 0.f, 0.f, 0.f);
    float ar16 = 0.0f, ai16 = 0.0f;

    for (int j = s; j < e; j++) {
        int cj = g_cols[j];
        float vj = g_vals[j];
        const float4* __restrict__ base = (const float4*)(g_bufB + (size_t)cj * FP_);
#pragma unroll
        for (int k = 0; k < 8; k++) {
            float4 t = base[k*32 + lane];
            acc[k].x = fmaf(vj, t.x, acc[k].x);
            acc[k].y = fmaf(vj, t.y, acc[k].y);
            acc[k].z = fmaf(vj, t.z, acc[k].z);
            acc[k].w = fmaf(vj, t.w, acc[k].w);
        }
        if (lane == 0) {
            float2 t = g_bufB[(size_t)cj*FP_ + 512];
            ar16 = fmaf(vj, t.x, ar16);
            ai16 = fmaf(vj, t.y, ai16);
        }
    }

    float px = rpos[3*row+0], py = rpos[3*row+1], pz = rpos[3*row+2];
    float rx = px - rcpos[0], ry = py - rcpos[1], rz = pz - rcpos[2];
    float dr = sqrtf(rx*rx + ry*ry + rz*rz);
    float br = c_c32() * (dr * c_s32());
    float wamp = __expf(c_kdec() * dr) / (dr*dr + 0.001f);

    float sx, cx;
    sc_big(br * (float)(lane*2), sx, cx);
    float2 w0 = make_float2(cx, sx);
    sc_big(br * (float)(lane*2 + 1), sx, cx);
    float2 w1 = make_float2(cx, sx);
    sc_big(br * 64.0f, sx, cx);
    float2 wst = make_float2(cx, sx);

    float4* outp = (float4*)(g_bufA + (size_t)row*FP_);
#pragma unroll
    for (int k = 0; k < 8; k++) {
        int f = k*64 + lane*2;
        __stcs(&outp[k*32 + lane], acc[k]);
        float2 e0 = cmul(make_float2(acc[k].x, acc[k].y), w0);
        float2 e1 = cmul(make_float2(acc[k].z, acc[k].w), w1);
        *(float4*)&esh[w][f] = make_float4(wamp*e0.x, wamp*e0.y, wamp*e1.x, wamp*e1.y);
        w0 = cmul(w0, wst);
        w1 = cmul(w1, wst);
    }
    // after 8 steps: w0 = e^{i br (lane*2 + 512)} -> lane 0 = f 512
    if (lane == 0) {
        __stcs(&g_bufA[(size_t)row*FP_ + 512], make_float2(ar16, ai16));
        float2 e0 = cmul(make_float2(ar16, ai16), w0);
        esh[w][512] = make_float2(wamp*e0.x, wamp*e0.y);
    }
    __syncthreads();
    for (int f = threadIdx.x; f < F_; f += 256) {
        float sr = 0.0f, si = 0.0f;
#pragma unroll
        for (int ww = 0; ww < 8; ww++) { sr += esh[ww][f].x; si += esh[ww][f].y; }
        atomicAdd(&g_echo[2*f  ], sr);
        atomicAdd(&g_echo[2*f+1], si);
    }
}

// ---------------- final: irfft(echo) / fsm_window (+ rowcnt re-zero) ----------
__global__ void __launch_bounds__(1024) k_ifft() {
    __shared__ float twc[T_], tws[T_];
    __shared__ float2 es[32];
    int t = threadIdx.x, b = blockIdx.x;
    g_rowcnt[b*1024 + t] = 0;                 // restore replay invariant
    {
        float th = (float)(2.0*3.14159265358979323846/1024.0) * (float)t;
        float s, c; __sincosf(th, &s, &c);
        twc[t] = c; tws[t] = s;
    }
    if (t < 32) {
        int k = b*32 + 1 + t;
        float2 v = make_float2(g_echo[2*k], g_echo[2*k+1]);
        if (k == 512) { v.x *= 0.5f; v.y *= 0.5f; }
        es[t] = v;
    }
    __syncthreads();
    float sum = 0.0f;
#pragma unroll 8
    for (int i = 0; i < 32; i++) {
        int k = b*32 + 1 + i;
        int m = (k * t) & 1023;
        float2 X = es[i];
        sum = fmaf(2.0f * X.x, twc[m], sum);
        sum = fmaf(-2.0f * X.y, tws[m], sum);
    }
    atomicAdd(&g_time[t], sum);
}

__global__ void __launch_bounds__(1024) k_scale(float* __restrict__ out) {
    int t = threadIdx.x;
    float v = (g_time[t] + g_echo[0]) * (1.0f / 1024.0f);
    float ta = (float)t / 16000.0f;
    float fsm = __expf(LOG_GAMMA_F * ta);
    out[t] = v / fsm;
}

// ---------------- launcher ----------------------------------------------------
extern "C" void kernel_launch(void* const* d_in, const int* in_sizes, int n_in,
                              void* d_out, int out_size) {
    const float* spos  = (const float*)d_in[0];
    const float* rcpos = (const float*)d_in[1];
    const float* absorb= (const float*)d_in[2];
    const float* scat  = (const float*)d_in[3];
    const float* gkv   = (const float*)d_in[4];
    const float* basis = (const float*)d_in[5];
    const float* avg   = (const float*)d_in[6];
    const float* rpos  = (const float*)d_in[7];
    const int*   gkr   = (const int*)d_in[8];
    const int*   gkc   = (const int*)d_in[9];
    const int*   obj   = (const int*)d_in[10];

    k_setup<<<(P_*D_*D_)/256, 256>>>(basis, absorb, scat, obj, gkr);   // 1
    k_rad<<<R_/8, 256>>>(rpos, spos, rcpos);                           // 2
    k_scan<<<1, 1024>>>();                                             // 3
    k_gemm_tc<<<dim3(P_, 16), 512>>>(avg);                             // 4  <- profile target
    k_scatter<<<E_/256, 256>>>(gkr, gkc, gkv);                         // 5
    k_gemm_last<<<P_, 128>>>(avg);                                     // 6
    k_spmm<<<R_/8, 256>>>(rpos, rcpos);                                // 7
    for (int b = 1; b < 4; b++) {
        k_gemm_tc<<<dim3(P_, 16), 512>>>(avg);
        k_gemm_last<<<P_, 128>>>(avg);
        k_spmm<<<R_/8, 256>>>(rpos, rcpos);
    }
    k_ifft<<<16, 1024>>>();
    k_scale<<<1, 1024>>>((float*)d_out);
}

// round 17
// speedup vs baseline: 1.8618x; 1.0157x over previous
#include <cuda_runtime.h>
#include <cuda_bf16.h>
#include <cstdint>

#define P_  128
#define D_  128
#define R_  16384
#define E_  131072
#define T_  1024
#define F_  513
#define FP_ 520     // padded row stride in float2 (16B-aligned rows)

// ---------------- scratch (static device allocations; no cudaMalloc) ----------
static __device__ __align__(16) float2 g_bufA[R_*FP_ + 256];   // r_k (single-use: stream)
static __device__ __align__(16) float2 g_bufB[R_*FP_ + 256];   // prop*(K r) (8x reuse: cache)
static __device__ __align__(16) float  g_K[P_*D_*D_];          // [p][e][d] (f=512 path)
static __device__ __align__(16) uint4  g_AfragHi[P_*8*8*32];   // mma-fragment-ordered K (hi)
static __device__ __align__(16) uint4  g_AfragLo[P_*8*8*32];   // mma-fragment-ordered K (lo)
static __device__ __align__(16) int g_rowptr[R_+4];
static __device__ __align__(16) int g_rowcnt[R_];              // zeroed by k_ifft each call
static __device__ int    g_rank[E_];                           // edge rank within its row
static __device__ int    g_cols[E_];
static __device__ float  g_vals[E_];
static __device__ float  g_echo[2*F_];                         // zeroed by k_ifft/k_scale
static __device__ float  g_time[T_];                           // zeroed by k_scale

// ---------------- constants matching reference fp32 rounding ------------------
__device__ __forceinline__ float c_s32()  { return (float)(16000.0/343.0); }
__device__ __forceinline__ float c_c32()  { return (float)(-2.0*3.14159265358979323846/1024.0); }
__device__ __forceinline__ float c_kdec() { return (float)(-6.907755278982137/343.0 - 0.001); }
#define LOG_GAMMA_F (-6.907755278982137f)

__device__ __forceinline__ void sc_big(float x, float& s, float& c) {
    float k = rintf(x * 0.15915494309189535f);
    float r = fmaf(k, -6.28125f, x);
    r = fmaf(k, -1.9353071795864769e-3f, r);
    __sincosf(r, &s, &c);
}

__device__ __forceinline__ float2 cmul(float2 a, float2 b) {
    return make_float2(a.x*b.x - a.y*b.y, a.x*b.y + a.y*b.x);
}

__device__ __forceinline__ uint32_t smem_u32(const void* p) {
    uint32_t a;
    asm("{ .reg .u64 t; cvta.to.shared.u64 t, %1; cvt.u32.u64 %0, t; }" : "=r"(a) : "l"(p));
    return a;
}

__device__ __forceinline__ uint32_t pk_bf2(float a, float b) {
    __nv_bfloat16 ha = __float2bfloat16(a), hb = __float2bfloat16(b);
    return ((uint32_t)__bfloat16_as_ushort(hb) << 16) | __bfloat16_as_ushort(ha);
}
__device__ __forceinline__ uint32_t pk_bf2_lo(float a, float b) {
    __nv_bfloat16 ha = __float2bfloat16(a), hb = __float2bfloat16(b);
    float ra = a - __bfloat162float(ha);
    float rb = b - __bfloat162float(hb);
    __nv_bfloat16 la = __float2bfloat16(ra), lb = __float2bfloat16(rb);
    return ((uint32_t)__bfloat16_as_ushort(lb) << 16) | __bfloat16_as_ushort(la);
}

// base-ISA tensor ops (sm_80+/75+, valid in compute_103 PTX)
__device__ __forceinline__ void mma_bf16(float& d0, float& d1, float& d2, float& d3,
                                         uint32_t a0, uint32_t a1, uint32_t a2, uint32_t a3,
                                         uint32_t b0, uint32_t b1) {
    asm volatile("mma.sync.aligned.m16n8k16.row.col.f32.bf16.bf16.f32 "
                 "{%0,%1,%2,%3}, {%4,%5,%6,%7}, {%8,%9}, {%0,%1,%2,%3};"
                 : "+f"(d0), "+f"(d1), "+f"(d2), "+f"(d3)
                 : "r"(a0), "r"(a1), "r"(a2), "r"(a3), "r"(b0), "r"(b1));
}
__device__ __forceinline__ void ldsm_x4_t(uint32_t& r0, uint32_t& r1, uint32_t& r2, uint32_t& r3,
                                          uint32_t addr) {
    asm volatile("ldmatrix.sync.aligned.m8n8.x4.trans.shared.b16 {%0,%1,%2,%3}, [%4];"
                 : "=r"(r0), "=r"(r1), "=r"(r2), "=r"(r3) : "r"(addr));
}

// ---------------- fused setup: K builds, CSR hist+rank, rad -------------------
// grid 8192 x 256. Blocks 0..2047 additionally run the rad body (independent).
__global__ void __launch_bounds__(256) k_setup(
        const float* __restrict__ basis, const float* __restrict__ absorb,
        const float* __restrict__ scat, const int* __restrict__ obj,
        const int* __restrict__ gkr,
        const float* __restrict__ rpos, const float* __restrict__ spos,
        const float* __restrict__ rcpos) {
    __shared__ __align__(16) float2 esh[8][520];
    int idx = blockIdx.x * blockDim.x + threadIdx.x;

    if (idx < E_) g_rank[idx] = atomicAdd(&g_rowcnt[gkr[idx]], 1);

    if (idx < P_*8*8*32) {   // mma-fragment-ordered bf16 hi/lo A
        int lane = idx & 31;
        int dt = (idx >> 5) & 7;
        int s  = (idx >> 8) & 7;
        int p  = idx >> 11;
        int o = obj[p];
        float refl = 1.0f - absorb[o];
        float c0 = refl * scat[o];
        float c1 = refl * (1.0f - scat[o]);
        int r  = lane >> 2, cq = lane & 3;
        int d0 = dt*16 + r, d1 = d0 + 8;
        int k0 = s*16 + cq*2;
#define KV(d, e) (c0 * basis[(d)*D_ + (e)] + c1 * basis[D_*D_ + (d)*D_ + (e)])
        float v00 = KV(d0, k0),     v01 = KV(d0, k0+1);
        float v10 = KV(d1, k0),     v11 = KV(d1, k0+1);
        float v02 = KV(d0, k0+8),   v03 = KV(d0, k0+9);
        float v12 = KV(d1, k0+8),   v13 = KV(d1, k0+9);
        g_AfragHi[idx] = make_uint4(pk_bf2(v00,v01), pk_bf2(v10,v11),
                                    pk_bf2(v02,v03), pk_bf2(v12,v13));
        g_AfragLo[idx] = make_uint4(pk_bf2_lo(v00,v01), pk_bf2_lo(v10,v11),
                                    pk_bf2_lo(v02,v03), pk_bf2_lo(v12,v13));
    }

    if (idx < P_*D_*D_) {   // fp32 K for the f=512 path
        int p = idx / (D_*D_);
        int rem = idx - p*D_*D_;
        int e = rem / D_;
        int d = rem - e*D_;
        int o = obj[p];
        float refl = 1.0f - absorb[o];
        float c0 = refl * scat[o];
        float c1 = refl * (1.0f - scat[o]);
        g_K[idx] = c0 * basis[d*D_ + e] + c1 * basis[D_*D_ + d*D_ + e];
#undef KV
    }

    // ---- rad (blocks 0..2047): bufA = rad, echo += w_rec*pf_rec*rad ----
    if (blockIdx.x < R_/8) {
        int w = threadIdx.x >> 5, lane = threadIdx.x & 31;
        int row = blockIdx.x * 8 + w;

        float px = rpos[3*row+0], py = rpos[3*row+1], pz = rpos[3*row+2];
        float dx = px - spos[0], dy = py - spos[1], dz = pz - spos[2];
        float ds = sqrtf(dx*dx + dy*dy + dz*dz);
        float bs = c_c32() * (ds * c_s32());
        float amp = __expf(c_kdec() * ds) / (ds*ds + 0.001f);

        float rx = px - rcpos[0], ry = py - rcpos[1], rz = pz - rcpos[2];
        float dr = sqrtf(rx*rx + ry*ry + rz*rz);
        float br = c_c32() * (dr * c_s32());
        float wamp = __expf(c_kdec() * dr) / (dr*dr + 0.001f);

        float s0, c0;
        sc_big(bs * (float)lane, s0, c0);
        float2 wsrc = make_float2(c0, s0);
        sc_big(bs * 32.0f, s0, c0);
        float2 wsstep = make_float2(c0, s0);
        sc_big(br * (float)lane, s0, c0);
        float2 wrec = make_float2(c0, s0);
        sc_big(br * 32.0f, s0, c0);
        float2 wrstep = make_float2(c0, s0);

#pragma unroll
        for (int k = 0; k < 16; k++) {
            int f = k*32 + lane;
            float2 rad = make_float2(amp * wsrc.x, amp * wsrc.y);
            __stcs(&g_bufA[(size_t)row*FP_ + f], rad);
            float2 er = cmul(rad, wrec);
            esh[w][f] = make_float2(wamp * er.x, wamp * er.y);
            wsrc = cmul(wsrc, wsstep);
            wrec = cmul(wrec, wrstep);
        }
        if (lane == 0) {
            float2 rad = make_float2(amp * wsrc.x, amp * wsrc.y);
            __stcs(&g_bufA[(size_t)row*FP_ + 512], rad);
            float2 er = cmul(rad, wrec);
            esh[w][512] = make_float2(wamp * er.x, wamp * er.y);
        }
        __syncthreads();
        for (int f = threadIdx.x; f < F_; f += 256) {
            float sr = 0.0f, si = 0.0f;
#pragma unroll
            for (int ww = 0; ww < 8; ww++) { sr += esh[ww][f].x; si += esh[ww][f].y; }
            atomicAdd(&g_echo[2*f  ], sr);
            atomicAdd(&g_echo[2*f+1], si);
        }
    }
}

__global__ void __launch_bounds__(1024) k_scan() {
    __shared__ int wsum[32];
    int t = threadIdx.x, lane = t & 31, wid = t >> 5;
    int4 v[4];
    const int4* src = (const int4*)g_rowcnt;
#pragma unroll
    for (int i = 0; i < 4; i++) v[i] = src[t*4 + i];
    const int* x = (const int*)v;
    int loc[16], sum = 0;
#pragma unroll
    for (int i = 0; i < 16; i++) { loc[i] = sum; sum += x[i]; }
    int incl = sum;
#pragma unroll
    for (int off = 1; off < 32; off <<= 1) {
        int n = __shfl_up_sync(0xffffffffu, incl, off);
        if (lane >= off) incl += n;
    }
    if (lane == 31) wsum[wid] = incl;
    __syncthreads();
    if (wid == 0) {
        int ws = wsum[lane];
#pragma unroll
        for (int off = 1; off < 32; off <<= 1) {
            int n = __shfl_up_sync(0xffffffffu, ws, off);
            if (lane >= off) ws += n;
        }
        wsum[lane] = ws;
    }
    __syncthreads();
    int off0 = (wid > 0 ? wsum[wid-1] : 0) + (incl - sum);
    int4 o[4];
    int* op = (int*)o;
#pragma unroll
    for (int i = 0; i < 16; i++) op[i] = off0 + loc[i];
    int4* dst = (int4*)g_rowptr;
    int4* cz  = (int4*)g_rowcnt;
    int4 z = make_int4(0,0,0,0);
#pragma unroll
    for (int i = 0; i < 4; i++) { dst[t*4 + i] = o[i]; cz[t*4 + i] = z; }
    if (t == 1023) g_rowptr[R_] = wsum[31];
}

// ---------------- tensor GEMM (fused): bufB = prop*(K_p @ bufA) ---------------
// grid (P_, 16), 512 thr, 2 blocks/SM. ft==15 blocks also do the f=512 column.
// do_scatter!=0 (bounce 1): blocks also scatter a 64-edge CSR slice (rank-based).
#define BP_ 144   // B row pitch bytes — conflict-free STS.128 + ldmatrix
__global__ void __launch_bounds__(512, 2) k_gemm_tc(const float* __restrict__ avg_dist,
                                                    const int* __restrict__ gkr,
                                                    const int* __restrict__ gkc,
                                                    const float* __restrict__ gkv,
                                                    int do_scatter) {
    __shared__ __align__(16) unsigned char Bhi[128*BP_];
    __shared__ __align__(16) unsigned char Blo[128*BP_];
    __shared__ __align__(16) float2 xs512[128];
    int p = blockIdx.x, ft = blockIdx.y, f0 = ft*32;
    int tid = threadIdx.x, w = tid >> 5, lane = tid & 31;
    int wd = w & 7, wn = w >> 3;

    if (do_scatter) {           // bounce-1 side duty: atomic-free CSR scatter
        int bid = blockIdx.y * P_ + blockIdx.x;
        if (tid < 64) {
            int e = bid*64 + tid;
            int pos = g_rowptr[gkr[e]] + g_rank[e];
            g_cols[pos] = gkc[e];
            g_vals[pos] = gkv[e];
        }
    }

    // ---- stage B (bufA single-use: streaming loads)
    {
        int k = tid >> 2, q = tid & 3;
        const float4* src = (const float4*)(g_bufA + (size_t)(p*128 + k)*FP_ + f0) + q*4;
        uint32_t hi[8], lo[8];
#pragma unroll
        for (int j = 0; j < 4; j++) {
            float4 v = __ldcs(src + j);
            hi[2*j]   = pk_bf2(v.x, v.y);
            hi[2*j+1] = pk_bf2(v.z, v.w);
            lo[2*j]   = pk_bf2_lo(v.x, v.y);
            lo[2*j+1] = pk_bf2_lo(v.z, v.w);
        }
        uint4* dh = (uint4*)(Bhi + k*BP_ + q*32);
        uint4* dl = (uint4*)(Blo + k*BP_ + q*32);
        dh[0] = make_uint4(hi[0], hi[1], hi[2], hi[3]);
        dh[1] = make_uint4(hi[4], hi[5], hi[6], hi[7]);
        dl[0] = make_uint4(lo[0], lo[1], lo[2], lo[3]);
        dl[1] = make_uint4(lo[4], lo[5], lo[6], lo[7]);
    }
    __syncthreads();

    float acc[4][4];
#pragma unroll
    for (int j = 0; j < 4; j++)
#pragma unroll
        for (int q = 0; q < 4; q++) acc[j][q] = 0.0f;

    int g = lane >> 3, lr = lane & 7;
    uint32_t rowoff = (uint32_t)(((g & 1)*8 + lr) * BP_);
    uint32_t bs_hi = smem_u32(Bhi), bs_lo = smem_u32(Blo);
    uint32_t co0 = bs_hi + rowoff + (uint32_t)((wn*32 +  0 + (g >> 1)*8) * 2);
    uint32_t co1 = bs_hi + rowoff + (uint32_t)((wn*32 + 16 + (g >> 1)*8) * 2);
    uint32_t cl0 = bs_lo + rowoff + (uint32_t)((wn*32 +  0 + (g >> 1)*8) * 2);
    uint32_t cl1 = bs_lo + rowoff + (uint32_t)((wn*32 + 16 + (g >> 1)*8) * 2);

    const uint4* Ah = g_AfragHi + ((size_t)p * 8) * 8 * 32;
    const uint4* Al = g_AfragLo + ((size_t)p * 8) * 8 * 32;

#pragma unroll
    for (int s = 0; s < 8; s++) {
        uint4 ah = Ah[((s*8) + wd)*32 + lane];
        uint4 al = Al[((s*8) + wd)*32 + lane];
        uint32_t soff = (uint32_t)(s * 16 * BP_);
        uint32_t bh[8], bl[8];
        ldsm_x4_t(bh[0], bh[1], bh[2], bh[3], co0 + soff);
        ldsm_x4_t(bh[4], bh[5], bh[6], bh[7], co1 + soff);
        ldsm_x4_t(bl[0], bl[1], bl[2], bl[3], cl0 + soff);
        ldsm_x4_t(bl[4], bl[5], bl[6], bl[7], cl1 + soff);
#pragma unroll
        for (int nt = 0; nt < 4; nt++) {
            mma_bf16(acc[nt][0], acc[nt][1], acc[nt][2], acc[nt][3],
                     ah.x, ah.y, ah.z, ah.w, bh[2*nt], bh[2*nt+1]);
            mma_bf16(acc[nt][0], acc[nt][1], acc[nt][2], acc[nt][3],
                     ah.x, ah.y, ah.z, ah.w, bl[2*nt], bl[2*nt+1]);
            mma_bf16(acc[nt][0], acc[nt][1], acc[nt][2], acc[nt][3],
                     al.x, al.y, al.z, al.w, bh[2*nt], bh[2*nt+1]);
        }
    }

    // ---- epilogue with phase recurrence (stride 4 in f per nt step)
    int r0 = lane >> 2, fq = lane & 3;
#pragma unroll
    for (int half = 0; half < 2; half++) {
        int d = wd*16 + half*8 + r0;
        int row = p*128 + d;
        float dist = avg_dist[row];
        float b = c_c32() * (dist * c_s32());
        float dec = __expf(c_kdec() * dist);
        float2* outp = g_bufB + (size_t)row*FP_ + f0 + wn*16;
        int fbase = f0 + wn*16 + fq;
        float ss, cc;
        sc_big(b * (float)fbase, ss, cc);
        float2 wp = make_float2(dec * cc, dec * ss);
        sc_big(b * 4.0f, ss, cc);
        float2 wst = make_float2(cc, ss);
#pragma unroll
        for (int nt = 0; nt < 4; nt++) {
            float2 v = cmul(make_float2(acc[nt][half*2 + 0], acc[nt][half*2 + 1]), wp);
            outp[nt*4 + fq] = v;
            wp = cmul(wp, wst);
        }
    }

    // ---- f = 512 column (ft == 15 blocks only; fp32 path)
    if (ft == 15) {
        __syncthreads();
        if (tid < 128) xs512[tid] = __ldcs(&g_bufA[(size_t)(p*128 + tid)*FP_ + 512]);
        __syncthreads();
        if (tid < 128) {
            int d = tid;
            const float* Kp = g_K + (size_t)p * D_ * D_;
            float ar = 0.0f, ai = 0.0f;
#pragma unroll 8
            for (int e = 0; e < 128; e++) {
                float kv = Kp[e*128 + d];
                float2 x = xs512[e];
                ar = fmaf(kv, x.x, ar);
                ai = fmaf(kv, x.y, ai);
            }
            int row = p*128 + d;
            float dist = avg_dist[row];
            float b = c_c32() * (dist * c_s32());
            float dec = __expf(c_kdec() * dist);
            float ss, cc; sc_big(b * 512.0f, ss, cc);
            float pr = dec * cc, pi = dec * ss;
            g_bufB[(size_t)row*FP_ + 512] = make_float2(pr*ar - pi*ai, pr*ai + pi*ar);
        }
    }
}

// ---------------- SpMM: bufA = A @ bufB, echo += w_rec*pf_rec*bufA ------------
// edge-outer float4 gathers (bufB cached, 8x reuse); bufA written streaming.
__global__ void __launch_bounds__(256) k_spmm(const float* __restrict__ rpos,
                                              const float* __restrict__ rcpos) {
    __shared__ __align__(16) float2 esh[8][520];
    int w = threadIdx.x >> 5, lane = threadIdx.x & 31;
    int row = blockIdx.x * 8 + w;
    int s = g_rowptr[row], e = g_rowptr[row+1];

    float4 acc[8];
#pragma unroll
    for (int k = 0; k < 8; k++) acc[k] = make_float4(0.f, 0.f, 0.f, 0.f);
    float ar16 = 0.0f, ai16 = 0.0f;

    for (int j = s; j < e; j++) {
        int cj = g_cols[j];
        float vj = g_vals[j];
        const float4* __restrict__ base = (const float4*)(g_bufB + (size_t)cj * FP_);
#pragma unroll
        for (int k = 0; k < 8; k++) {
            float4 t = base[k*32 + lane];
            acc[k].x = fmaf(vj, t.x, acc[k].x);
            acc[k].y = fmaf(vj, t.y, acc[k].y);
            acc[k].z = fmaf(vj, t.z, acc[k].z);
            acc[k].w = fmaf(vj, t.w, acc[k].w);
        }
        if (lane == 0) {
            float2 t = g_bufB[(size_t)cj*FP_ + 512];
            ar16 = fmaf(vj, t.x, ar16);
            ai16 = fmaf(vj, t.y, ai16);
        }
    }

    float px = rpos[3*row+0], py = rpos[3*row+1], pz = rpos[3*row+2];
    float rx = px - rcpos[0], ry = py - rcpos[1], rz = pz - rcpos[2];
    float dr = sqrtf(rx*rx + ry*ry + rz*rz);
    float br = c_c32() * (dr * c_s32());
    float wamp = __expf(c_kdec() * dr) / (dr*dr + 0.001f);

    float sx, cx;
    sc_big(br * (float)(lane*2), sx, cx);
    float2 w0 = make_float2(cx, sx);
    sc_big(br * (float)(lane*2 + 1), sx, cx);
    float2 w1 = make_float2(cx, sx);
    sc_big(br * 64.0f, sx, cx);
    float2 wst = make_float2(cx, sx);

    float4* outp = (float4*)(g_bufA + (size_t)row*FP_);
#pragma unroll
    for (int k = 0; k < 8; k++) {
        int f = k*64 + lane*2;
        __stcs(&outp[k*32 + lane], acc[k]);
        float2 e0 = cmul(make_float2(acc[k].x, acc[k].y), w0);
        float2 e1 = cmul(make_float2(acc[k].z, acc[k].w), w1);
        *(float4*)&esh[w][f] = make_float4(wamp*e0.x, wamp*e0.y, wamp*e1.x, wamp*e1.y);
        w0 = cmul(w0, wst);
        w1 = cmul(w1, wst);
    }
    if (lane == 0) {
        __stcs(&g_bufA[(size_t)row*FP_ + 512], make_float2(ar16, ai16));
        float2 e0 = cmul(make_float2(ar16, ai16), w0);
        esh[w][512] = make_float2(wamp*e0.x, wamp*e0.y);
    }
    __syncthreads();
    for (int f = threadIdx.x; f < F_; f += 256) {
        float sr = 0.0f, si = 0.0f;
#pragma unroll
        for (int ww = 0; ww < 8; ww++) { sr += esh[ww][f].x; si += esh[ww][f].y; }
        atomicAdd(&g_echo[2*f  ], sr);
        atomicAdd(&g_echo[2*f+1], si);
    }
}

// ---------------- final: irfft(echo) / fsm_window; restores invariants --------
__global__ void __launch_bounds__(1024) k_ifft() {
    __shared__ float twc[T_], tws[T_];
    __shared__ float2 es[32];
    int t = threadIdx.x, b = blockIdx.x;
    g_rowcnt[b*1024 + t] = 0;                 // replay invariant
    {
        float th = (float)(2.0*3.14159265358979323846/1024.0) * (float)t;
        float s, c; __sincosf(th, &s, &c);
        twc[t] = c; tws[t] = s;
    }
    if (t < 32) {
        int k = b*32 + 1 + t;
        float2 v = make_float2(g_echo[2*k], g_echo[2*k+1]);
        if (k == 512) { v.x *= 0.5f; v.y *= 0.5f; }
        es[t] = v;
    }
    __syncthreads();
    if (t < 64) g_echo[b*64 + 2 + t] = 0.0f;  // zero own echo slice (post-load)
    float sum = 0.0f;
#pragma unroll 8
    for (int i = 0; i < 32; i++) {
        int k = b*32 + 1 + i;
        int m = (k * t) & 1023;
        float2 X = es[i];
        sum = fmaf(2.0f * X.x, twc[m], sum);
        sum = fmaf(-2.0f * X.y, tws[m], sum);
    }
    atomicAdd(&g_time[t], sum);
}

__global__ void __launch_bounds__(1024) k_scale(float* __restrict__ out) {
    int t = threadIdx.x;
    float v = (g_time[t] + g_echo[0]) * (1.0f / 1024.0f);
    g_time[t] = 0.0f;                          // replay invariant
    if (t < 2) g_echo[t] = 0.0f;
    float ta = (float)t / 16000.0f;
    float fsm = __expf(LOG_GAMMA_F * ta);
    out[t] = v / fsm;
}

// ---------------- launcher ----------------------------------------------------
extern "C" void kernel_launch(void* const* d_in, const int* in_sizes, int n_in,
                              void* d_out, int out_size) {
    const float* spos  = (const float*)d_in[0];
    const float* rcpos = (const float*)d_in[1];
    const float* absorb= (const float*)d_in[2];
    const float* scat  = (const float*)d_in[3];
    const float* gkv   = (const float*)d_in[4];
    const float* basis = (const float*)d_in[5];
    const float* avg   = (const float*)d_in[6];
    const float* rpos  = (const float*)d_in[7];
    const int*   gkr   = (const int*)d_in[8];
    const int*   gkc   = (const int*)d_in[9];
    const int*   obj   = (const int*)d_in[10];

    k_setup<<<(P_*D_*D_)/256, 256>>>(basis, absorb, scat, obj, gkr,
                                     rpos, spos, rcpos);                // 1 (incl. rad)
    k_scan<<<1, 1024>>>();                                              // 2
    k_gemm_tc<<<dim3(P_, 16), 512>>>(avg, gkr, gkc, gkv, 1);            // 3 (incl. scatter+f512)
    k_spmm<<<R_/8, 256>>>(rpos, rcpos);                                 // 4  <- profile target
    for (int b = 1; b < 4; b++) {
        k_gemm_tc<<<dim3(P_, 16), 512>>>(avg, gkr, gkc, gkv, 0);
        k_spmm<<<R_/8, 256>>>(rpos, rcpos);
    }
    k_ifft<<<16, 1024>>>();
    k_scale<<<1, 1024>>>((float*)d_out);
}